// round 1
// baseline (speedup 1.0000x reference)
#include <cuda_runtime.h>
#include <math.h>

#define HH 16
#define BB 8
#define SS 1024
#define DMOD 1024
#define DH 64
#define NQKV 3072   // 16 heads * (64+64+64)

// ---------------- scratch (device globals; no allocation allowed) ----------------
__device__ float g_W[DMOD * NQKV];          // packed [d][h*192 + j]  (12 MB)
__device__ float g_bias[NQKV];
__device__ float g_q[HH * BB * SS * DH];    // [h][b][s][c] (33.5 MB)
__device__ float g_k[HH * BB * SS * DH];
__device__ float g_v[HH * BB * SS * DH];
__device__ float g_ctx[SS * BB * DMOD];     // [s][b][h*64+v] (32 MB)

// ---------------- pack Wq/Wk/Wv (+biases) into one GEMM operand ----------------
__global__ void pack_kernel(const float* __restrict__ Wq, const float* __restrict__ bq,
                            const float* __restrict__ Wk, const float* __restrict__ bk,
                            const float* __restrict__ Wv, const float* __restrict__ bv)
{
    int idx = blockIdx.x * blockDim.x + threadIdx.x;
    if (idx >= DMOD * NQKV) return;
    int d = idx / NQKV, n = idx % NQKV;
    int h = n / 192, j = n % 192, t = j >> 6, c = j & 63;
    const float* Wsrc = (t == 0) ? Wq : (t == 1) ? Wk : Wv;
    g_W[idx] = Wsrc[(h * DMOD + d) * DH + c];
    if (idx < NQKV) {                    // d == 0 here, n == idx
        const float* bsrc = (t == 0) ? bq : (t == 1) ? bk : bv;
        g_bias[idx] = bsrc[h * DH + c];
    }
}

// ---------------- 128x128x8 register-tiled SGEMM ----------------
// MODE 1: A = param (Q, 8192x1024), B = g_W, bias = g_bias, scatter into g_q/g_k/g_v
// MODE 0: A = g_ctx (8192x1024),    B = param (Wo),  bias = param (bo), C = param (row-major)
template <int MODE>
__global__ void __launch_bounds__(256) sgemm_kernel(const float* __restrict__ Aparam,
                                                    const float* __restrict__ Bparam,
                                                    const float* __restrict__ biasparam,
                                                    float* __restrict__ C,
                                                    int M, int N, int K)
{
    const float* A    = (MODE == 1) ? Aparam : g_ctx;
    const float* Bmat = (MODE == 1) ? g_W    : Bparam;
    const float* bias = (MODE == 1) ? g_bias : biasparam;

    __shared__ float As[8][128];
    __shared__ float Bs[8][128];

    int tid = threadIdx.x;
    int ty = tid >> 4, tx = tid & 15;
    int rowBase = blockIdx.y * 128;
    int colBase = blockIdx.x * 128;

    int arow = tid >> 1, acol = (tid & 1) * 4;
    int brow = tid >> 5, bcol = (tid & 31) * 4;

    const float* Aptr = A + (size_t)(rowBase + arow) * K + acol;
    const float* Bptr = Bmat + (size_t)brow * N + colBase + bcol;

    float acc[8][8];
#pragma unroll
    for (int i = 0; i < 8; i++)
#pragma unroll
        for (int j = 0; j < 8; j++) acc[i][j] = 0.f;

    for (int k0 = 0; k0 < K; k0 += 8) {
        float4 av = *(const float4*)(Aptr + k0);
        As[acol + 0][arow] = av.x;
        As[acol + 1][arow] = av.y;
        As[acol + 2][arow] = av.z;
        As[acol + 3][arow] = av.w;
        float4 bv = *(const float4*)(Bptr + (size_t)k0 * N);
        *(float4*)&Bs[brow][bcol] = bv;
        __syncthreads();
#pragma unroll
        for (int kk = 0; kk < 8; kk++) {
            float4 a0 = *(const float4*)&As[kk][ty * 4];
            float4 a1 = *(const float4*)&As[kk][64 + ty * 4];
            float4 b0 = *(const float4*)&Bs[kk][tx * 4];
            float4 b1 = *(const float4*)&Bs[kk][64 + tx * 4];
            float a[8] = {a0.x, a0.y, a0.z, a0.w, a1.x, a1.y, a1.z, a1.w};
            float b[8] = {b0.x, b0.y, b0.z, b0.w, b1.x, b1.y, b1.z, b1.w};
#pragma unroll
            for (int i = 0; i < 8; i++)
#pragma unroll
                for (int j = 0; j < 8; j++) acc[i][j] = fmaf(a[i], b[j], acc[i][j]);
        }
        __syncthreads();
    }

    if (MODE == 0) {
#pragma unroll
        for (int i = 0; i < 8; i++) {
            int r = rowBase + ((i < 4) ? ty * 4 + i : 64 + ty * 4 + (i - 4));
#pragma unroll
            for (int jb = 0; jb < 2; jb++) {
                int cn = colBase + jb * 64 + tx * 4;
                float4 bv = *(const float4*)&bias[cn];
                float4 o;
                o.x = acc[i][jb * 4 + 0] + bv.x;
                o.y = acc[i][jb * 4 + 1] + bv.y;
                o.z = acc[i][jb * 4 + 2] + bv.z;
                o.w = acc[i][jb * 4 + 3] + bv.w;
                *(float4*)&C[(size_t)r * N + cn] = o;
            }
        }
    } else {
#pragma unroll
        for (int i = 0; i < 8; i++) {
            int r = rowBase + ((i < 4) ? ty * 4 + i : 64 + ty * 4 + (i - 4));
            int s = r >> 3, b = r & 7;
#pragma unroll
            for (int j = 0; j < 8; j++) {
                int n = colBase + ((j < 4) ? tx * 4 + j : 64 + tx * 4 + (j - 4));
                int h = n / 192, jj = n % 192, t = jj >> 6, c = jj & 63;
                float val = acc[i][j] + g_bias[n];
                int dst = ((h * BB + b) * SS + s) * DH + c;
                float* buf = (t == 0) ? g_q : (t == 1) ? g_k : g_v;
                buf[dst] = val;
            }
        }
    }
}

// ---------------- flash attention: 64x64 tiles, online softmax, causal ----------------
// grid: (16 qtiles, 128 head*batch), block 256 (16x16, 4x4 micro-tiles)
__global__ void __launch_bounds__(256) flash_kernel()
{
    extern __shared__ float sm[];
    float* QsT = sm;               // [64 kk][68]
    float* KsT = QsT + 64 * 68;    // [64 kk][68]
    float* Ps  = KsT + 64 * 68;    // [64 r ][68]
    float* Vs  = Ps  + 64 * 68;    // [64 c ][68]
    float* m_s = Vs  + 64 * 68;    // [64]
    float* l_s = m_s + 64;         // [64]

    int tid = threadIdx.x;
    int ty = tid >> 4, tx = tid & 15;
    int r0 = ty * 4, c0 = tx * 4;
    int qt = blockIdx.x;
    int hb = blockIdx.y;
    int h = hb >> 3, b = hb & 7;
    int qs0 = qt * 64;

    const float* qg  = g_q + (size_t)((h * BB + b) * SS + qs0) * DH;
    const float* kg0 = g_k + (size_t)(h * BB + b) * SS * DH;
    const float* vg0 = g_v + (size_t)(h * BB + b) * SS * DH;

    // load Q tile, pre-scaled by 1/sqrt(64), stored transposed (kk-major)
#pragma unroll
    for (int t = 0; t < 4; t++) {
        int f = tid + t * 256;
        int row = f >> 4, c4 = (f & 15) << 2;
        float4 v = *(const float4*)(qg + row * DH + c4);
        QsT[(c4 + 0) * 68 + row] = v.x * 0.125f;
        QsT[(c4 + 1) * 68 + row] = v.y * 0.125f;
        QsT[(c4 + 2) * 68 + row] = v.z * 0.125f;
        QsT[(c4 + 3) * 68 + row] = v.w * 0.125f;
    }
    if (tid < 64) { m_s[tid] = -INFINITY; l_s[tid] = 0.f; }
    float o[4][4] = {};
    __syncthreads();

    for (int kt = 0; kt <= qt; kt++) {
        const float* kg = kg0 + (size_t)kt * 64 * DH;
        const float* vg = vg0 + (size_t)kt * 64 * DH;
#pragma unroll
        for (int t = 0; t < 4; t++) {
            int f = tid + t * 256;
            int row = f >> 4, c4 = (f & 15) << 2;
            float4 kv = *(const float4*)(kg + row * DH + c4);
            KsT[(c4 + 0) * 68 + row] = kv.x;
            KsT[(c4 + 1) * 68 + row] = kv.y;
            KsT[(c4 + 2) * 68 + row] = kv.z;
            KsT[(c4 + 3) * 68 + row] = kv.w;
            float4 vv = *(const float4*)(vg + row * DH + c4);
            *(float4*)&Vs[row * 68 + c4] = vv;
        }
        __syncthreads();

        // scores: s[4][4] = Q_tile . K_tile^T (already scaled)
        float s[4][4] = {};
#pragma unroll 8
        for (int kk = 0; kk < 64; kk++) {
            float4 aq = *(const float4*)&QsT[kk * 68 + r0];
            float4 bk = *(const float4*)&KsT[kk * 68 + c0];
            float a[4] = {aq.x, aq.y, aq.z, aq.w};
            float bf[4] = {bk.x, bk.y, bk.z, bk.w};
#pragma unroll
            for (int i = 0; i < 4; i++)
#pragma unroll
                for (int j = 0; j < 4; j++) s[i][j] = fmaf(a[i], bf[j], s[i][j]);
        }

        if (kt == qt) {   // causal mask on the diagonal tile
#pragma unroll
            for (int i = 0; i < 4; i++)
#pragma unroll
                for (int j = 0; j < 4; j++)
                    if (c0 + j > r0 + i) s[i][j] = -1e30f;
        }

        // online softmax update (row groups of 16 lanes share a warp half)
#pragma unroll
        for (int i = 0; i < 4; i++) {
            float mloc = fmaxf(fmaxf(s[i][0], s[i][1]), fmaxf(s[i][2], s[i][3]));
#pragma unroll
            for (int off = 8; off; off >>= 1)
                mloc = fmaxf(mloc, __shfl_xor_sync(0xffffffffu, mloc, off, 16));
            float mold = m_s[r0 + i];
            float mnew = fmaxf(mold, mloc);
            float p0 = __expf(s[i][0] - mnew);
            float p1 = __expf(s[i][1] - mnew);
            float p2 = __expf(s[i][2] - mnew);
            float p3 = __expf(s[i][3] - mnew);
            float4 pw = {p0, p1, p2, p3};
            *(float4*)&Ps[(r0 + i) * 68 + c0] = pw;
            float rs = (p0 + p1) + (p2 + p3);
#pragma unroll
            for (int off = 8; off; off >>= 1)
                rs += __shfl_xor_sync(0xffffffffu, rs, off, 16);
            float alpha = __expf(mold - mnew);
#pragma unroll
            for (int j = 0; j < 4; j++) o[i][j] *= alpha;
            __syncwarp();
            if (tx == 0) {
                m_s[r0 + i] = mnew;
                l_s[r0 + i] = l_s[r0 + i] * alpha + rs;
            }
        }
        __syncthreads();

        // O += P @ V
#pragma unroll 8
        for (int c = 0; c < 64; c++) {
            float4 vv = *(const float4*)&Vs[c * 68 + c0];
            float p0 = Ps[(r0 + 0) * 68 + c];
            float p1 = Ps[(r0 + 1) * 68 + c];
            float p2 = Ps[(r0 + 2) * 68 + c];
            float p3 = Ps[(r0 + 3) * 68 + c];
            float bf[4] = {vv.x, vv.y, vv.z, vv.w};
            float p[4] = {p0, p1, p2, p3};
#pragma unroll
            for (int i = 0; i < 4; i++)
#pragma unroll
                for (int j = 0; j < 4; j++) o[i][j] = fmaf(p[i], bf[j], o[i][j]);
        }
        __syncthreads();
    }

    // epilogue: normalize and write into ctx [s][b][h*64+v]
#pragma unroll
    for (int i = 0; i < 4; i++) {
        float inv = 1.f / l_s[r0 + i];
        float4 w;
        w.x = o[i][0] * inv;
        w.y = o[i][1] * inv;
        w.z = o[i][2] * inv;
        w.w = o[i][3] * inv;
        *(float4*)&g_ctx[(size_t)((qs0 + r0 + i) * BB + b) * DMOD + h * DH + c0] = w;
    }
}

// ---------------- launch ----------------
extern "C" void kernel_launch(void* const* d_in, const int* in_sizes, int n_in,
                              void* d_out, int out_size)
{
    const float* Q  = (const float*)d_in[0];
    const float* Wq = (const float*)d_in[1];
    const float* bq = (const float*)d_in[2];
    const float* Wk = (const float*)d_in[3];
    const float* bk = (const float*)d_in[4];
    const float* Wv = (const float*)d_in[5];
    const float* bv = (const float*)d_in[6];
    const float* Wo = (const float*)d_in[7];
    const float* bo = (const float*)d_in[8];
    float* out = (float*)d_out;

    const int M = SS * BB;  // 8192

    // 1) pack weights
    pack_kernel<<<(DMOD * NQKV + 255) / 256, 256>>>(Wq, bq, Wk, bk, Wv, bv);

    // 2) QKV projection: (8192 x 1024) @ (1024 x 3072) -> scattered q/k/v
    {
        dim3 grid(NQKV / 128, M / 128);
        sgemm_kernel<1><<<grid, 256>>>(Q, nullptr, nullptr, nullptr, M, NQKV, DMOD);
    }

    // 3) causal flash attention -> g_ctx
    {
        size_t smem = (size_t)(64 * 68 * 4 + 128) * sizeof(float);  // ~70 KB
        cudaFuncSetAttribute(flash_kernel, cudaFuncAttributeMaxDynamicSharedMemorySize,
                             (int)(smem + 1024));
        flash_kernel<<<dim3(SS / 64, HH * BB), 256, smem>>>();
    }

    // 4) output projection: ctx (8192 x 1024) @ Wo (1024 x 1024) + bo -> out
    {
        dim3 grid(DMOD / 128, M / 128);
        sgemm_kernel<0><<<grid, 256>>>(nullptr, Wo, bo, out, M, DMOD, DMOD);
    }
}

// round 2
// speedup vs baseline: 1.0009x; 1.0009x over previous
#include <cuda_runtime.h>
#include <math.h>

#define HH 16
#define BB 8
#define SS 1024
#define DMOD 1024
#define DH 64
#define NQKV 3072   // 16 heads * (64+64+64)

// ---------------- scratch (device globals; no allocation allowed) ----------------
__device__ float g_W[DMOD * NQKV];          // packed [d][h*192 + j]  (12 MB)
__device__ float g_bias[NQKV];
__device__ float g_q[HH * BB * SS * DH];    // [h][b][s][c] (33.5 MB)
__device__ float g_k[HH * BB * SS * DH];
__device__ float g_v[HH * BB * SS * DH];
__device__ float g_ctx[SS * BB * DMOD];     // [s][b][h*64+v] (32 MB)

// ---------------- pack Wq/Wk/Wv (+biases) into one GEMM operand ----------------
__global__ void pack_kernel(const float* __restrict__ Wq, const float* __restrict__ bq,
                            const float* __restrict__ Wk, const float* __restrict__ bk,
                            const float* __restrict__ Wv, const float* __restrict__ bv)
{
    int idx = blockIdx.x * blockDim.x + threadIdx.x;
    if (idx >= DMOD * NQKV) return;
    int d = idx / NQKV, n = idx % NQKV;
    int h = n / 192, j = n % 192, t = j >> 6, c = j & 63;
    const float* Wsrc = (t == 0) ? Wq : (t == 1) ? Wk : Wv;
    g_W[idx] = Wsrc[(h * DMOD + d) * DH + c];
    if (idx < NQKV) {                    // d == 0 here, n == idx
        const float* bsrc = (t == 0) ? bq : (t == 1) ? bk : bv;
        g_bias[idx] = bsrc[h * DH + c];
    }
}

// ---------------- 128x128x8 register-tiled SGEMM ----------------
// MODE 1: A = param (Q, 8192x1024), B = g_W, bias = g_bias, scatter into g_q/g_k/g_v
// MODE 0: A = g_ctx (8192x1024),    B = param (Wo),  bias = param (bo), C = param (row-major)
template <int MODE>
__global__ void __launch_bounds__(256) sgemm_kernel(const float* __restrict__ Aparam,
                                                    const float* __restrict__ Bparam,
                                                    const float* __restrict__ biasparam,
                                                    float* __restrict__ C,
                                                    int M, int N, int K)
{
    const float* A    = (MODE == 1) ? Aparam : g_ctx;
    const float* Bmat = (MODE == 1) ? g_W    : Bparam;
    const float* bias = (MODE == 1) ? g_bias : biasparam;

    __shared__ float As[8][128];
    __shared__ float Bs[8][128];

    int tid = threadIdx.x;
    int ty = tid >> 4, tx = tid & 15;
    int rowBase = blockIdx.y * 128;
    int colBase = blockIdx.x * 128;

    int arow = tid >> 1, acol = (tid & 1) * 4;
    int brow = tid >> 5, bcol = (tid & 31) * 4;

    const float* Aptr = A + (size_t)(rowBase + arow) * K + acol;
    const float* Bptr = Bmat + (size_t)brow * N + colBase + bcol;

    float acc[8][8];
#pragma unroll
    for (int i = 0; i < 8; i++)
#pragma unroll
        for (int j = 0; j < 8; j++) acc[i][j] = 0.f;

    for (int k0 = 0; k0 < K; k0 += 8) {
        float4 av = *(const float4*)(Aptr + k0);
        As[acol + 0][arow] = av.x;
        As[acol + 1][arow] = av.y;
        As[acol + 2][arow] = av.z;
        As[acol + 3][arow] = av.w;
        float4 bv = *(const float4*)(Bptr + (size_t)k0 * N);
        *(float4*)&Bs[brow][bcol] = bv;
        __syncthreads();
#pragma unroll
        for (int kk = 0; kk < 8; kk++) {
            float4 a0 = *(const float4*)&As[kk][ty * 4];
            float4 a1 = *(const float4*)&As[kk][64 + ty * 4];
            float4 b0 = *(const float4*)&Bs[kk][tx * 4];
            float4 b1 = *(const float4*)&Bs[kk][64 + tx * 4];
            float a[8] = {a0.x, a0.y, a0.z, a0.w, a1.x, a1.y, a1.z, a1.w};
            float b[8] = {b0.x, b0.y, b0.z, b0.w, b1.x, b1.y, b1.z, b1.w};
#pragma unroll
            for (int i = 0; i < 8; i++)
#pragma unroll
                for (int j = 0; j < 8; j++) acc[i][j] = fmaf(a[i], b[j], acc[i][j]);
        }
        __syncthreads();
    }

    if (MODE == 0) {
#pragma unroll
        for (int i = 0; i < 8; i++) {
            int r = rowBase + ((i < 4) ? ty * 4 + i : 64 + ty * 4 + (i - 4));
#pragma unroll
            for (int jb = 0; jb < 2; jb++) {
                int cn = colBase + jb * 64 + tx * 4;
                float4 bv = *(const float4*)&bias[cn];
                float4 o;
                o.x = acc[i][jb * 4 + 0] + bv.x;
                o.y = acc[i][jb * 4 + 1] + bv.y;
                o.z = acc[i][jb * 4 + 2] + bv.z;
                o.w = acc[i][jb * 4 + 3] + bv.w;
                *(float4*)&C[(size_t)r * N + cn] = o;
            }
        }
    } else {
#pragma unroll
        for (int i = 0; i < 8; i++) {
            int r = rowBase + ((i < 4) ? ty * 4 + i : 64 + ty * 4 + (i - 4));
            int s = r >> 3, b = r & 7;
#pragma unroll
            for (int j = 0; j < 8; j++) {
                int n = colBase + ((j < 4) ? tx * 4 + j : 64 + tx * 4 + (j - 4));
                int h = n / 192, jj = n % 192, t = jj >> 6, c = jj & 63;
                float val = acc[i][j] + g_bias[n];
                int dst = ((h * BB + b) * SS + s) * DH + c;
                float* buf = (t == 0) ? g_q : (t == 1) ? g_k : g_v;
                buf[dst] = val;
            }
        }
    }
}

// ---------------- flash attention: 64x64 tiles, online softmax, causal ----------------
// grid: (16 qtiles, 128 head*batch), block 256 (16x16, 4x4 micro-tiles)
__global__ void __launch_bounds__(256) flash_kernel()
{
    extern __shared__ float sm[];
    float* QsT = sm;               // [64 kk][68]
    float* KsT = QsT + 64 * 68;    // [64 kk][68]
    float* Ps  = KsT + 64 * 68;    // [64 r ][68]
    float* Vs  = Ps  + 64 * 68;    // [64 c ][68]
    float* m_s = Vs  + 64 * 68;    // [64]
    float* l_s = m_s + 64;         // [64]

    int tid = threadIdx.x;
    int ty = tid >> 4, tx = tid & 15;
    int r0 = ty * 4, c0 = tx * 4;
    int qt = blockIdx.x;
    int hb = blockIdx.y;
    int h = hb >> 3, b = hb & 7;
    int qs0 = qt * 64;

    const float* qg  = g_q + (size_t)((h * BB + b) * SS + qs0) * DH;
    const float* kg0 = g_k + (size_t)(h * BB + b) * SS * DH;
    const float* vg0 = g_v + (size_t)(h * BB + b) * SS * DH;

    // load Q tile, pre-scaled by 1/sqrt(64), stored transposed (kk-major)
#pragma unroll
    for (int t = 0; t < 4; t++) {
        int f = tid + t * 256;
        int row = f >> 4, c4 = (f & 15) << 2;
        float4 v = *(const float4*)(qg + row * DH + c4);
        QsT[(c4 + 0) * 68 + row] = v.x * 0.125f;
        QsT[(c4 + 1) * 68 + row] = v.y * 0.125f;
        QsT[(c4 + 2) * 68 + row] = v.z * 0.125f;
        QsT[(c4 + 3) * 68 + row] = v.w * 0.125f;
    }
    if (tid < 64) { m_s[tid] = -INFINITY; l_s[tid] = 0.f; }
    float o[4][4] = {};
    __syncthreads();

    for (int kt = 0; kt <= qt; kt++) {
        const float* kg = kg0 + (size_t)kt * 64 * DH;
        const float* vg = vg0 + (size_t)kt * 64 * DH;
#pragma unroll
        for (int t = 0; t < 4; t++) {
            int f = tid + t * 256;
            int row = f >> 4, c4 = (f & 15) << 2;
            float4 kv = *(const float4*)(kg + row * DH + c4);
            KsT[(c4 + 0) * 68 + row] = kv.x;
            KsT[(c4 + 1) * 68 + row] = kv.y;
            KsT[(c4 + 2) * 68 + row] = kv.z;
            KsT[(c4 + 3) * 68 + row] = kv.w;
            float4 vv = *(const float4*)(vg + row * DH + c4);
            *(float4*)&Vs[row * 68 + c4] = vv;
        }
        __syncthreads();

        // scores: s[4][4] = Q_tile . K_tile^T (already scaled)
        float s[4][4] = {};
#pragma unroll 8
        for (int kk = 0; kk < 64; kk++) {
            float4 aq = *(const float4*)&QsT[kk * 68 + r0];
            float4 bk = *(const float4*)&KsT[kk * 68 + c0];
            float a[4] = {aq.x, aq.y, aq.z, aq.w};
            float bf[4] = {bk.x, bk.y, bk.z, bk.w};
#pragma unroll
            for (int i = 0; i < 4; i++)
#pragma unroll
                for (int j = 0; j < 4; j++) s[i][j] = fmaf(a[i], bf[j], s[i][j]);
        }

        if (kt == qt) {   // causal mask on the diagonal tile
#pragma unroll
            for (int i = 0; i < 4; i++)
#pragma unroll
                for (int j = 0; j < 4; j++)
                    if (c0 + j > r0 + i) s[i][j] = -1e30f;
        }

        // online softmax update (row groups of 16 lanes share a warp half)
#pragma unroll
        for (int i = 0; i < 4; i++) {
            float mloc = fmaxf(fmaxf(s[i][0], s[i][1]), fmaxf(s[i][2], s[i][3]));
#pragma unroll
            for (int off = 8; off; off >>= 1)
                mloc = fmaxf(mloc, __shfl_xor_sync(0xffffffffu, mloc, off, 16));
            float mold = m_s[r0 + i];
            float mnew = fmaxf(mold, mloc);
            float p0 = __expf(s[i][0] - mnew);
            float p1 = __expf(s[i][1] - mnew);
            float p2 = __expf(s[i][2] - mnew);
            float p3 = __expf(s[i][3] - mnew);
            float4 pw = {p0, p1, p2, p3};
            *(float4*)&Ps[(r0 + i) * 68 + c0] = pw;
            float rs = (p0 + p1) + (p2 + p3);
#pragma unroll
            for (int off = 8; off; off >>= 1)
                rs += __shfl_xor_sync(0xffffffffu, rs, off, 16);
            float alpha = __expf(mold - mnew);
#pragma unroll
            for (int j = 0; j < 4; j++) o[i][j] *= alpha;
            __syncwarp();
            if (tx == 0) {
                m_s[r0 + i] = mnew;
                l_s[r0 + i] = l_s[r0 + i] * alpha + rs;
            }
        }
        __syncthreads();

        // O += P @ V
#pragma unroll 8
        for (int c = 0; c < 64; c++) {
            float4 vv = *(const float4*)&Vs[c * 68 + c0];
            float p0 = Ps[(r0 + 0) * 68 + c];
            float p1 = Ps[(r0 + 1) * 68 + c];
            float p2 = Ps[(r0 + 2) * 68 + c];
            float p3 = Ps[(r0 + 3) * 68 + c];
            float bf[4] = {vv.x, vv.y, vv.z, vv.w};
            float p[4] = {p0, p1, p2, p3};
#pragma unroll
            for (int i = 0; i < 4; i++)
#pragma unroll
                for (int j = 0; j < 4; j++) o[i][j] = fmaf(p[i], bf[j], o[i][j]);
        }
        __syncthreads();
    }

    // epilogue: normalize and write into ctx [s][b][h*64+v]
#pragma unroll
    for (int i = 0; i < 4; i++) {
        float inv = 1.f / l_s[r0 + i];
        float4 w;
        w.x = o[i][0] * inv;
        w.y = o[i][1] * inv;
        w.z = o[i][2] * inv;
        w.w = o[i][3] * inv;
        *(float4*)&g_ctx[(size_t)((qs0 + r0 + i) * BB + b) * DMOD + h * DH + c0] = w;
    }
}

// ---------------- launch ----------------
extern "C" void kernel_launch(void* const* d_in, const int* in_sizes, int n_in,
                              void* d_out, int out_size)
{
    const float* Q  = (const float*)d_in[0];
    const float* Wq = (const float*)d_in[1];
    const float* bq = (const float*)d_in[2];
    const float* Wk = (const float*)d_in[3];
    const float* bk = (const float*)d_in[4];
    const float* Wv = (const float*)d_in[5];
    const float* bv = (const float*)d_in[6];
    const float* Wo = (const float*)d_in[7];
    const float* bo = (const float*)d_in[8];
    float* out = (float*)d_out;

    const int M = SS * BB;  // 8192

    // 1) pack weights
    pack_kernel<<<(DMOD * NQKV + 255) / 256, 256>>>(Wq, bq, Wk, bk, Wv, bv);

    // 2) QKV projection: (8192 x 1024) @ (1024 x 3072) -> scattered q/k/v
    {
        dim3 grid(NQKV / 128, M / 128);
        sgemm_kernel<1><<<grid, 256>>>(Q, nullptr, nullptr, nullptr, M, NQKV, DMOD);
    }

    // 3) causal flash attention -> g_ctx
    {
        size_t smem = (size_t)(64 * 68 * 4 + 128) * sizeof(float);  // ~70 KB
        cudaFuncSetAttribute(flash_kernel, cudaFuncAttributeMaxDynamicSharedMemorySize,
                             (int)(smem + 1024));
        flash_kernel<<<dim3(SS / 64, HH * BB), 256, smem>>>();
    }

    // 4) output projection: ctx (8192 x 1024) @ Wo (1024 x 1024) + bo -> out
    {
        dim3 grid(DMOD / 128, M / 128);
        sgemm_kernel<0><<<grid, 256>>>(nullptr, Wo, bo, out, M, DMOD, DMOD);
    }
}

// round 3
// speedup vs baseline: 1.7992x; 1.7976x over previous
#include <cuda_runtime.h>
#include <math.h>
#include <stdint.h>

#define HH 16
#define BB 8
#define SS 1024
#define DMOD 1024
#define DH 64
#define NQKV 3072   // 16 heads * (64+64+64)

// ---------------- scratch (device globals; no allocation allowed) ----------------
__device__ float g_W[DMOD * NQKV];          // packed [d][h*192 + j]
__device__ float g_bias[NQKV];
__device__ float g_q[HH * BB * SS * DH];    // [h][b][s][c]
__device__ float g_k[HH * BB * SS * DH];
__device__ float g_v[HH * BB * SS * DH];
__device__ float g_ctx[SS * BB * DMOD];     // [s][b][h*64+v]

// ---------------- pack Wq/Wk/Wv (+biases) into one GEMM operand ----------------
__global__ void pack_kernel(const float* __restrict__ Wq, const float* __restrict__ bq,
                            const float* __restrict__ Wk, const float* __restrict__ bk,
                            const float* __restrict__ Wv, const float* __restrict__ bv)
{
    int idx = blockIdx.x * blockDim.x + threadIdx.x;
    if (idx >= DMOD * NQKV) return;
    int d = idx / NQKV, n = idx % NQKV;
    int h = n / 192, j = n % 192, t = j >> 6, c = j & 63;
    const float* Wsrc = (t == 0) ? Wq : (t == 1) ? Wk : Wv;
    g_W[idx] = Wsrc[(h * DMOD + d) * DH + c];
    if (idx < NQKV) {
        const float* bsrc = (t == 0) ? bq : (t == 1) ? bk : bv;
        g_bias[idx] = bsrc[h * DH + c];
    }
}

// ---------------- TF32 tensor-core GEMM ----------------
// Block tile 128x128x32; 8 warps, each warp 64x32 via 4x4 m16n8k8 mma tiles.
// MODE 1: A = param (Q, 8192x1024), B = g_W, bias = g_bias, scatter into g_q/g_k/g_v
// MODE 0: A = g_ctx,                B = param (Wo), bias = param (bo), C row-major

#define BM 128
#define BN 128
#define BK 32
#define AS_STRIDE 36    // bank = (4g + tg) mod 32 -> conflict-free fragment loads
#define BS_STRIDE 136   // bank = (8tg + g) mod 32 -> conflict-free fragment loads

__device__ __forceinline__ uint32_t f2tf32(float x) {
    uint32_t u;
    asm("cvt.rna.tf32.f32 %0, %1;" : "=r"(u) : "f"(x));
    return u;
}

__device__ __forceinline__ void store_tile(uint32_t* as, uint32_t* bs,
                                           const float4* ra, const float4* rb,
                                           int ar, int ac4, int bk, int bn4)
{
#pragma unroll
    for (int i = 0; i < 4; i++) {
        int r = ar + 32 * i;
        uint32_t* p = as + r * AS_STRIDE + ac4;
        p[0] = f2tf32(ra[i].x);
        p[1] = f2tf32(ra[i].y);
        p[2] = f2tf32(ra[i].z);
        p[3] = f2tf32(ra[i].w);
        int k = bk + 8 * i;
        uint32_t* q = bs + k * BS_STRIDE + bn4;
        q[0] = f2tf32(rb[i].x);
        q[1] = f2tf32(rb[i].y);
        q[2] = f2tf32(rb[i].z);
        q[3] = f2tf32(rb[i].w);
    }
}

template <int MODE>
__global__ void __launch_bounds__(256) tf32_gemm(const float* __restrict__ Aparam,
                                                 const float* __restrict__ Bparam,
                                                 const float* __restrict__ biasparam,
                                                 float* __restrict__ C,
                                                 int M, int N, int K)
{
    extern __shared__ uint32_t smem[];
    uint32_t* AsBase = smem;                          // 2 * 128*36
    uint32_t* BsBase = smem + 2 * BM * AS_STRIDE;     // 2 * 32*136

    const float* A    = (MODE == 1) ? Aparam : g_ctx;
    const float* Bmat = (MODE == 1) ? g_W    : Bparam;

    int tid = threadIdx.x;
    int warp = tid >> 5, lane = tid & 31;
    int wm = warp >> 2, wn = warp & 3;          // 2 x 4 warp grid
    int g = lane >> 2, tg = lane & 3;
    int rowBase = blockIdx.y * BM;
    int colBase = blockIdx.x * BN;

    // global-load indices
    int ar  = tid >> 3;            // + 32*i  -> rows 0..127
    int ac4 = (tid & 7) * 4;       // cols 0..28 step 4 (within BK)
    int bk  = tid >> 5;            // + 8*i   -> k rows 0..31
    int bn4 = (tid & 31) * 4;      // cols 0..124 step 4 (within BN)

    const float* Ag = A + (size_t)rowBase * K;
    const float* Bg = Bmat + colBase;

    float acc[4][4][4];
#pragma unroll
    for (int mi = 0; mi < 4; mi++)
#pragma unroll
        for (int ni = 0; ni < 4; ni++)
#pragma unroll
            for (int r = 0; r < 4; r++) acc[mi][ni][r] = 0.f;

    float4 ra[4], rb[4];
    // prefetch tile 0
#pragma unroll
    for (int i = 0; i < 4; i++) {
        ra[i] = *(const float4*)(Ag + (size_t)(ar + 32 * i) * K + ac4);
        rb[i] = *(const float4*)(Bg + (size_t)(bk + 8 * i) * N + bn4);
    }
    store_tile(AsBase, BsBase, ra, rb, ar, ac4, bk, bn4);
    __syncthreads();

    const int ntiles = K / BK;
    int buf = 0;
    for (int t = 0; t < ntiles; t++) {
        if (t + 1 < ntiles) {
            int k0 = (t + 1) * BK;
#pragma unroll
            for (int i = 0; i < 4; i++) {
                ra[i] = *(const float4*)(Ag + (size_t)(ar + 32 * i) * K + k0 + ac4);
                rb[i] = *(const float4*)(Bg + (size_t)(k0 + bk + 8 * i) * N + bn4);
            }
        }
        const uint32_t* as = AsBase + buf * BM * AS_STRIDE;
        const uint32_t* bs = BsBase + buf * BK * BS_STRIDE;

#pragma unroll
        for (int ks = 0; ks < 4; ks++) {
            uint32_t afrag[4][4], bfrag[4][2];
#pragma unroll
            for (int mi = 0; mi < 4; mi++) {
                int rr = wm * 64 + mi * 16;
                const uint32_t* p  = as + (rr + g) * AS_STRIDE + ks * 8 + tg;
                const uint32_t* p2 = p + 8 * AS_STRIDE;
                afrag[mi][0] = p[0];    // (g,   tg)
                afrag[mi][1] = p2[0];   // (g+8, tg)
                afrag[mi][2] = p[4];    // (g,   tg+4)
                afrag[mi][3] = p2[4];   // (g+8, tg+4)
            }
#pragma unroll
            for (int ni = 0; ni < 4; ni++) {
                int nn = wn * 32 + ni * 8 + g;
                bfrag[ni][0] = bs[(ks * 8 + tg) * BS_STRIDE + nn];
                bfrag[ni][1] = bs[(ks * 8 + tg + 4) * BS_STRIDE + nn];
            }
#pragma unroll
            for (int mi = 0; mi < 4; mi++)
#pragma unroll
                for (int ni = 0; ni < 4; ni++) {
                    asm volatile(
                        "mma.sync.aligned.m16n8k8.row.col.f32.tf32.tf32.f32 "
                        "{%0,%1,%2,%3}, {%4,%5,%6,%7}, {%8,%9}, {%0,%1,%2,%3};"
                        : "+f"(acc[mi][ni][0]), "+f"(acc[mi][ni][1]),
                          "+f"(acc[mi][ni][2]), "+f"(acc[mi][ni][3])
                        : "r"(afrag[mi][0]), "r"(afrag[mi][1]),
                          "r"(afrag[mi][2]), "r"(afrag[mi][3]),
                          "r"(bfrag[ni][0]), "r"(bfrag[ni][1]));
                }
        }
        if (t + 1 < ntiles)
            store_tile(AsBase + (buf ^ 1) * BM * AS_STRIDE,
                       BsBase + (buf ^ 1) * BK * BS_STRIDE, ra, rb, ar, ac4, bk, bn4);
        __syncthreads();
        buf ^= 1;
    }

    // epilogue: c0=(g,2tg) c1=(g,2tg+1) c2=(g+8,2tg) c3=(g+8,2tg+1)
#pragma unroll
    for (int mi = 0; mi < 4; mi++) {
#pragma unroll
        for (int ni = 0; ni < 4; ni++) {
            int r0 = rowBase + wm * 64 + mi * 16 + g;
            int cn = colBase + wn * 32 + ni * 8 + tg * 2;
            if (MODE == 0) {
                float2 bv = *(const float2*)&biasparam[cn];
                float2 o0 = {acc[mi][ni][0] + bv.x, acc[mi][ni][1] + bv.y};
                float2 o1 = {acc[mi][ni][2] + bv.x, acc[mi][ni][3] + bv.y};
                *(float2*)&C[(size_t)r0 * N + cn] = o0;
                *(float2*)&C[(size_t)(r0 + 8) * N + cn] = o1;
            } else {
#pragma unroll
                for (int e = 0; e < 4; e++) {
                    int r = r0 + (e >> 1) * 8;
                    int n = cn + (e & 1);
                    int s = r >> 3, b = r & 7;
                    int h = n / 192, jj = n % 192, ty = jj >> 6, c = jj & 63;
                    float val = acc[mi][ni][e] + g_bias[n];
                    float* bufp = (ty == 0) ? g_q : (ty == 1) ? g_k : g_v;
                    bufp[((h * BB + b) * SS + s) * DH + c] = val;
                }
            }
        }
    }
}

// ---------------- flash attention: 64x64 tiles, online softmax, causal ----------------
__global__ void __launch_bounds__(256) flash_kernel()
{
    extern __shared__ float sm[];
    float* QsT = sm;               // [64 kk][68]
    float* KsT = QsT + 64 * 68;    // [64 kk][68]
    float* Ps  = KsT + 64 * 68;    // [64 r ][68]
    float* Vs  = Ps  + 64 * 68;    // [64 c ][68]
    float* m_s = Vs  + 64 * 68;    // [64]
    float* l_s = m_s + 64;         // [64]

    int tid = threadIdx.x;
    int ty = tid >> 4, tx = tid & 15;
    int r0 = ty * 4, c0 = tx * 4;
    int qt = blockIdx.x;
    int hb = blockIdx.y;
    int h = hb >> 3, b = hb & 7;
    int qs0 = qt * 64;

    const float* qg  = g_q + (size_t)((h * BB + b) * SS + qs0) * DH;
    const float* kg0 = g_k + (size_t)(h * BB + b) * SS * DH;
    const float* vg0 = g_v + (size_t)(h * BB + b) * SS * DH;

#pragma unroll
    for (int t = 0; t < 4; t++) {
        int f = tid + t * 256;
        int row = f >> 4, c4 = (f & 15) << 2;
        float4 v = *(const float4*)(qg + row * DH + c4);
        QsT[(c4 + 0) * 68 + row] = v.x * 0.125f;
        QsT[(c4 + 1) * 68 + row] = v.y * 0.125f;
        QsT[(c4 + 2) * 68 + row] = v.z * 0.125f;
        QsT[(c4 + 3) * 68 + row] = v.w * 0.125f;
    }
    if (tid < 64) { m_s[tid] = -INFINITY; l_s[tid] = 0.f; }
    float o[4][4] = {};
    __syncthreads();

    for (int kt = 0; kt <= qt; kt++) {
        const float* kg = kg0 + (size_t)kt * 64 * DH;
        const float* vg = vg0 + (size_t)kt * 64 * DH;
#pragma unroll
        for (int t = 0; t < 4; t++) {
            int f = tid + t * 256;
            int row = f >> 4, c4 = (f & 15) << 2;
            float4 kv = *(const float4*)(kg + row * DH + c4);
            KsT[(c4 + 0) * 68 + row] = kv.x;
            KsT[(c4 + 1) * 68 + row] = kv.y;
            KsT[(c4 + 2) * 68 + row] = kv.z;
            KsT[(c4 + 3) * 68 + row] = kv.w;
            float4 vv = *(const float4*)(vg + row * DH + c4);
            *(float4*)&Vs[row * 68 + c4] = vv;
        }
        __syncthreads();

        float s[4][4] = {};
#pragma unroll 8
        for (int kk = 0; kk < 64; kk++) {
            float4 aq = *(const float4*)&QsT[kk * 68 + r0];
            float4 bk = *(const float4*)&KsT[kk * 68 + c0];
            float a[4] = {aq.x, aq.y, aq.z, aq.w};
            float bf[4] = {bk.x, bk.y, bk.z, bk.w};
#pragma unroll
            for (int i = 0; i < 4; i++)
#pragma unroll
                for (int j = 0; j < 4; j++) s[i][j] = fmaf(a[i], bf[j], s[i][j]);
        }

        if (kt == qt) {
#pragma unroll
            for (int i = 0; i < 4; i++)
#pragma unroll
                for (int j = 0; j < 4; j++)
                    if (c0 + j > r0 + i) s[i][j] = -1e30f;
        }

#pragma unroll
        for (int i = 0; i < 4; i++) {
            float mloc = fmaxf(fmaxf(s[i][0], s[i][1]), fmaxf(s[i][2], s[i][3]));
#pragma unroll
            for (int off = 8; off; off >>= 1)
                mloc = fmaxf(mloc, __shfl_xor_sync(0xffffffffu, mloc, off, 16));
            float mold = m_s[r0 + i];
            float mnew = fmaxf(mold, mloc);
            float p0 = __expf(s[i][0] - mnew);
            float p1 = __expf(s[i][1] - mnew);
            float p2 = __expf(s[i][2] - mnew);
            float p3 = __expf(s[i][3] - mnew);
            float4 pw = {p0, p1, p2, p3};
            *(float4*)&Ps[(r0 + i) * 68 + c0] = pw;
            float rs = (p0 + p1) + (p2 + p3);
#pragma unroll
            for (int off = 8; off; off >>= 1)
                rs += __shfl_xor_sync(0xffffffffu, rs, off, 16);
            float alpha = __expf(mold - mnew);
#pragma unroll
            for (int j = 0; j < 4; j++) o[i][j] *= alpha;
            __syncwarp();
            if (tx == 0) {
                m_s[r0 + i] = mnew;
                l_s[r0 + i] = l_s[r0 + i] * alpha + rs;
            }
        }
        __syncthreads();

#pragma unroll 8
        for (int c = 0; c < 64; c++) {
            float4 vv = *(const float4*)&Vs[c * 68 + c0];
            float p0 = Ps[(r0 + 0) * 68 + c];
            float p1 = Ps[(r0 + 1) * 68 + c];
            float p2 = Ps[(r0 + 2) * 68 + c];
            float p3 = Ps[(r0 + 3) * 68 + c];
            float bf[4] = {vv.x, vv.y, vv.z, vv.w};
            float p[4] = {p0, p1, p2, p3};
#pragma unroll
            for (int i = 0; i < 4; i++)
#pragma unroll
                for (int j = 0; j < 4; j++) o[i][j] = fmaf(p[i], bf[j], o[i][j]);
        }
        __syncthreads();
    }

#pragma unroll
    for (int i = 0; i < 4; i++) {
        float inv = 1.f / l_s[r0 + i];
        float4 w;
        w.x = o[i][0] * inv;
        w.y = o[i][1] * inv;
        w.z = o[i][2] * inv;
        w.w = o[i][3] * inv;
        *(float4*)&g_ctx[(size_t)((qs0 + r0 + i) * BB + b) * DMOD + h * DH + c0] = w;
    }
}

// ---------------- launch ----------------
extern "C" void kernel_launch(void* const* d_in, const int* in_sizes, int n_in,
                              void* d_out, int out_size)
{
    const float* Q  = (const float*)d_in[0];
    const float* Wq = (const float*)d_in[1];
    const float* bq = (const float*)d_in[2];
    const float* Wk = (const float*)d_in[3];
    const float* bk = (const float*)d_in[4];
    const float* Wv = (const float*)d_in[5];
    const float* bv = (const float*)d_in[6];
    const float* Wo = (const float*)d_in[7];
    const float* bo = (const float*)d_in[8];
    float* out = (float*)d_out;

    const int M = SS * BB;  // 8192
    const size_t gemm_smem = (size_t)(2 * BM * AS_STRIDE + 2 * BK * BS_STRIDE) * 4;  // ~70KB

    // 1) pack weights
    pack_kernel<<<(DMOD * NQKV + 255) / 256, 256>>>(Wq, bq, Wk, bk, Wv, bv);

    // 2) QKV projection (tf32 tensor cores): (8192x1024) @ (1024x3072) -> q/k/v
    {
        cudaFuncSetAttribute(tf32_gemm<1>, cudaFuncAttributeMaxDynamicSharedMemorySize,
                             (int)gemm_smem);
        dim3 grid(NQKV / BN, M / BM);
        tf32_gemm<1><<<grid, 256, gemm_smem>>>(Q, nullptr, nullptr, nullptr, M, NQKV, DMOD);
    }

    // 3) causal flash attention -> g_ctx
    {
        size_t smem = (size_t)(64 * 68 * 4 + 128) * sizeof(float);
        cudaFuncSetAttribute(flash_kernel, cudaFuncAttributeMaxDynamicSharedMemorySize,
                             (int)(smem + 1024));
        flash_kernel<<<dim3(SS / 64, HH * BB), 256, smem>>>();
    }

    // 4) output projection (tf32 tensor cores): ctx (8192x1024) @ Wo + bo -> out
    {
        cudaFuncSetAttribute(tf32_gemm<0>, cudaFuncAttributeMaxDynamicSharedMemorySize,
                             (int)gemm_smem);
        dim3 grid(DMOD / BN, M / BM);
        tf32_gemm<0><<<grid, 256, gemm_smem>>>(nullptr, Wo, bo, out, M, DMOD, DMOD);
    }
}

// round 4
// speedup vs baseline: 2.7110x; 1.5068x over previous
#include <cuda_runtime.h>
#include <math.h>
#include <stdint.h>

#define HH 16
#define BB 8
#define SS 1024
#define DMOD 1024
#define DH 64
#define NQKV 3072   // 16 heads * (64+64+64)

// ---------------- scratch (device globals; no allocation allowed) ----------------
__device__ float g_W[DMOD * NQKV];          // packed [d][h*192 + j]
__device__ float g_bias[NQKV];
__device__ float g_q[HH * BB * SS * DH];    // [h][b][s][c]
__device__ float g_k[HH * BB * SS * DH];
__device__ float g_v[HH * BB * SS * DH];
__device__ float g_ctx[SS * BB * DMOD];     // [s][b][h*64+v]

__device__ __forceinline__ uint32_t f2tf32(float x) {
    uint32_t u;
    asm("cvt.rna.tf32.f32 %0, %1;" : "=r"(u) : "f"(x));
    return u;
}

__device__ __forceinline__ void mma_tf32(float* d, const uint32_t* a,
                                         uint32_t b0, uint32_t b1) {
    asm volatile(
        "mma.sync.aligned.m16n8k8.row.col.f32.tf32.tf32.f32 "
        "{%0,%1,%2,%3}, {%4,%5,%6,%7}, {%8,%9}, {%0,%1,%2,%3};"
        : "+f"(d[0]), "+f"(d[1]), "+f"(d[2]), "+f"(d[3])
        : "r"(a[0]), "r"(a[1]), "r"(a[2]), "r"(a[3]), "r"(b0), "r"(b1));
}

// ---------------- pack Wq/Wk/Wv (+biases) into one GEMM operand ----------------
__global__ void pack_kernel(const float* __restrict__ Wq, const float* __restrict__ bq,
                            const float* __restrict__ Wk, const float* __restrict__ bk,
                            const float* __restrict__ Wv, const float* __restrict__ bv)
{
    int idx = blockIdx.x * blockDim.x + threadIdx.x;
    if (idx >= DMOD * NQKV) return;
    int d = idx / NQKV, n = idx % NQKV;
    int h = n / 192, j = n % 192, t = j >> 6, c = j & 63;
    const float* Wsrc = (t == 0) ? Wq : (t == 1) ? Wk : Wv;
    g_W[idx] = Wsrc[(h * DMOD + d) * DH + c];
    if (idx < NQKV) {
        const float* bsrc = (t == 0) ? bq : (t == 1) ? bk : bv;
        g_bias[idx] = bsrc[h * DH + c];
    }
}

// ---------------- TF32 tensor-core GEMM (unchanged from R2) ----------------
#define BM 128
#define BN 128
#define BK 32
#define AS_STRIDE 36
#define BS_STRIDE 136

__device__ __forceinline__ void store_tile(uint32_t* as, uint32_t* bs,
                                           const float4* ra, const float4* rb,
                                           int ar, int ac4, int bk, int bn4)
{
#pragma unroll
    for (int i = 0; i < 4; i++) {
        int r = ar + 32 * i;
        uint32_t* p = as + r * AS_STRIDE + ac4;
        p[0] = f2tf32(ra[i].x);
        p[1] = f2tf32(ra[i].y);
        p[2] = f2tf32(ra[i].z);
        p[3] = f2tf32(ra[i].w);
        int k = bk + 8 * i;
        uint32_t* q = bs + k * BS_STRIDE + bn4;
        q[0] = f2tf32(rb[i].x);
        q[1] = f2tf32(rb[i].y);
        q[2] = f2tf32(rb[i].z);
        q[3] = f2tf32(rb[i].w);
    }
}

template <int MODE>
__global__ void __launch_bounds__(256) tf32_gemm(const float* __restrict__ Aparam,
                                                 const float* __restrict__ Bparam,
                                                 const float* __restrict__ biasparam,
                                                 float* __restrict__ C,
                                                 int M, int N, int K)
{
    extern __shared__ uint32_t smem[];
    uint32_t* AsBase = smem;
    uint32_t* BsBase = smem + 2 * BM * AS_STRIDE;

    const float* A    = (MODE == 1) ? Aparam : g_ctx;
    const float* Bmat = (MODE == 1) ? g_W    : Bparam;

    int tid = threadIdx.x;
    int warp = tid >> 5, lane = tid & 31;
    int wm = warp >> 2, wn = warp & 3;
    int g = lane >> 2, tg = lane & 3;
    int rowBase = blockIdx.y * BM;
    int colBase = blockIdx.x * BN;

    int ar  = tid >> 3;
    int ac4 = (tid & 7) * 4;
    int bk  = tid >> 5;
    int bn4 = (tid & 31) * 4;

    const float* Ag = A + (size_t)rowBase * K;
    const float* Bg = Bmat + colBase;

    float acc[4][4][4];
#pragma unroll
    for (int mi = 0; mi < 4; mi++)
#pragma unroll
        for (int ni = 0; ni < 4; ni++)
#pragma unroll
            for (int r = 0; r < 4; r++) acc[mi][ni][r] = 0.f;

    float4 ra[4], rb[4];
#pragma unroll
    for (int i = 0; i < 4; i++) {
        ra[i] = *(const float4*)(Ag + (size_t)(ar + 32 * i) * K + ac4);
        rb[i] = *(const float4*)(Bg + (size_t)(bk + 8 * i) * N + bn4);
    }
    store_tile(AsBase, BsBase, ra, rb, ar, ac4, bk, bn4);
    __syncthreads();

    const int ntiles = K / BK;
    int buf = 0;
    for (int t = 0; t < ntiles; t++) {
        if (t + 1 < ntiles) {
            int k0 = (t + 1) * BK;
#pragma unroll
            for (int i = 0; i < 4; i++) {
                ra[i] = *(const float4*)(Ag + (size_t)(ar + 32 * i) * K + k0 + ac4);
                rb[i] = *(const float4*)(Bg + (size_t)(k0 + bk + 8 * i) * N + bn4);
            }
        }
        const uint32_t* as = AsBase + buf * BM * AS_STRIDE;
        const uint32_t* bs = BsBase + buf * BK * BS_STRIDE;

#pragma unroll
        for (int ks = 0; ks < 4; ks++) {
            uint32_t afrag[4][4], bfrag[4][2];
#pragma unroll
            for (int mi = 0; mi < 4; mi++) {
                int rr = wm * 64 + mi * 16;
                const uint32_t* p  = as + (rr + g) * AS_STRIDE + ks * 8 + tg;
                const uint32_t* p2 = p + 8 * AS_STRIDE;
                afrag[mi][0] = p[0];
                afrag[mi][1] = p2[0];
                afrag[mi][2] = p[4];
                afrag[mi][3] = p2[4];
            }
#pragma unroll
            for (int ni = 0; ni < 4; ni++) {
                int nn = wn * 32 + ni * 8 + g;
                bfrag[ni][0] = bs[(ks * 8 + tg) * BS_STRIDE + nn];
                bfrag[ni][1] = bs[(ks * 8 + tg + 4) * BS_STRIDE + nn];
            }
#pragma unroll
            for (int mi = 0; mi < 4; mi++)
#pragma unroll
                for (int ni = 0; ni < 4; ni++)
                    mma_tf32(acc[mi][ni], afrag[mi], bfrag[ni][0], bfrag[ni][1]);
        }
        if (t + 1 < ntiles)
            store_tile(AsBase + (buf ^ 1) * BM * AS_STRIDE,
                       BsBase + (buf ^ 1) * BK * BS_STRIDE, ra, rb, ar, ac4, bk, bn4);
        __syncthreads();
        buf ^= 1;
    }

#pragma unroll
    for (int mi = 0; mi < 4; mi++) {
#pragma unroll
        for (int ni = 0; ni < 4; ni++) {
            int r0 = rowBase + wm * 64 + mi * 16 + g;
            int cn = colBase + wn * 32 + ni * 8 + tg * 2;
            if (MODE == 0) {
                float2 bv = *(const float2*)&biasparam[cn];
                float2 o0 = {acc[mi][ni][0] + bv.x, acc[mi][ni][1] + bv.y};
                float2 o1 = {acc[mi][ni][2] + bv.x, acc[mi][ni][3] + bv.y};
                *(float2*)&C[(size_t)r0 * N + cn] = o0;
                *(float2*)&C[(size_t)(r0 + 8) * N + cn] = o1;
            } else {
#pragma unroll
                for (int e = 0; e < 4; e++) {
                    int r = r0 + (e >> 1) * 8;
                    int n = cn + (e & 1);
                    int s = r >> 3, b = r & 7;
                    int h = n / 192, jj = n % 192, ty = jj >> 6, c = jj & 63;
                    float val = acc[mi][ni][e] + g_bias[n];
                    float* bufp = (ty == 0) ? g_q : (ty == 1) ? g_k : g_v;
                    bufp[((h * BB + b) * SS + s) * DH + c] = val;
                }
            }
        }
    }
}

// ---------------- TF32 tensor-core flash attention ----------------
// Block: 128 q rows, 8 warps x 16 rows. K/V tiles of 64 keys in smem (tf32).
// Q held in registers as A-fragments for the whole kernel. Online softmax in
// registers; P goes through a warp-private smem region to re-shape C->A layout.
#define KSTRIDE 68   // bank(4g+tg) bijective for K B-frag loads
#define VSTRIDE 72   // bank(8tg+g) bijective for V B-frag loads
#define PSTRIDE 68   // bank(4g+tg) bijective for P A-frag loads

__global__ void __launch_bounds__(256) flash_tf32()
{
    extern __shared__ uint32_t sm[];
    uint32_t* Ks = sm;                    // [64][KSTRIDE]
    uint32_t* Vs = Ks + 64 * KSTRIDE;     // [64][VSTRIDE]
    uint32_t* Ps = Vs + 64 * VSTRIDE;     // [128][PSTRIDE]

    int tid = threadIdx.x;
    int warp = tid >> 5, lane = tid & 31;
    int g = lane >> 2, tg = lane & 3;
    int qx = blockIdx.x;                  // 0..7 (128-row q tiles)
    int hb = blockIdx.y;
    int h = hb >> 3, b = hb & 7;
    int qs0 = qx * 128;
    int wr = warp * 16;

    const float* qg  = g_q + ((size_t)(h * BB + b) * SS + qs0) * DH;
    const float* kg0 = g_k + (size_t)(h * BB + b) * SS * DH;
    const float* vg0 = g_v + (size_t)(h * BB + b) * SS * DH;

    // Q A-fragments, pre-scaled by 1/sqrt(64)
    uint32_t aq[8][4];
#pragma unroll
    for (int ki = 0; ki < 8; ki++) {
        const float* qp = qg + (wr + g) * DH + ki * 8 + tg;
        aq[ki][0] = f2tf32(qp[0] * 0.125f);
        aq[ki][1] = f2tf32(qp[8 * DH] * 0.125f);
        aq[ki][2] = f2tf32(qp[4] * 0.125f);
        aq[ki][3] = f2tf32(qp[8 * DH + 4] * 0.125f);
    }

    float o[8][4];
#pragma unroll
    for (int ni = 0; ni < 8; ni++)
#pragma unroll
        for (int e = 0; e < 4; e++) o[ni][e] = 0.f;
    float m_lo = -INFINITY, m_hi = -INFINITY, l_lo = 0.f, l_hi = 0.f;

    const int nkt = 2 * (qx + 1);
    for (int kt = 0; kt < nkt; kt++) {
        const float* kg = kg0 + (size_t)kt * 64 * DH;
        const float* vg = vg0 + (size_t)kt * 64 * DH;
        __syncthreads();   // prior-iteration mma done reading Ks/Vs
#pragma unroll
        for (int t = 0; t < 4; t++) {
            int f = tid + t * 256;
            int row = f >> 4, c4 = (f & 15) << 2;
            float4 kv = *(const float4*)(kg + row * DH + c4);
            uint32_t* kp = Ks + row * KSTRIDE + c4;
            kp[0] = f2tf32(kv.x); kp[1] = f2tf32(kv.y);
            kp[2] = f2tf32(kv.z); kp[3] = f2tf32(kv.w);
            float4 vv = *(const float4*)(vg + row * DH + c4);
            uint32_t* vp = Vs + row * VSTRIDE + c4;
            vp[0] = f2tf32(vv.x); vp[1] = f2tf32(vv.y);
            vp[2] = f2tf32(vv.z); vp[3] = f2tf32(vv.w);
        }
        __syncthreads();

        // scores 16x64 per warp
        float sc[8][4];
#pragma unroll
        for (int ni = 0; ni < 8; ni++)
#pragma unroll
            for (int e = 0; e < 4; e++) sc[ni][e] = 0.f;
#pragma unroll
        for (int ki = 0; ki < 8; ki++) {
#pragma unroll
            for (int ni = 0; ni < 8; ni++) {
                const uint32_t* kb = Ks + (ni * 8 + g) * KSTRIDE + ki * 8 + tg;
                mma_tf32(sc[ni], aq[ki], kb[0], kb[4]);
            }
        }

        // causal mask (only diagonal-region tiles)
        if (kt * 64 + 63 > qs0 + wr) {
            int rlo = qs0 + wr + g, rhi = rlo + 8;
#pragma unroll
            for (int ni = 0; ni < 8; ni++) {
                int col = kt * 64 + ni * 8 + 2 * tg;
                if (col     > rlo) sc[ni][0] = -1e30f;
                if (col + 1 > rlo) sc[ni][1] = -1e30f;
                if (col     > rhi) sc[ni][2] = -1e30f;
                if (col + 1 > rhi) sc[ni][3] = -1e30f;
            }
        }

        // online softmax (rows g and g+8, replicated across quad lanes)
        float mx_lo = -1e30f, mx_hi = -1e30f;
#pragma unroll
        for (int ni = 0; ni < 8; ni++) {
            mx_lo = fmaxf(mx_lo, fmaxf(sc[ni][0], sc[ni][1]));
            mx_hi = fmaxf(mx_hi, fmaxf(sc[ni][2], sc[ni][3]));
        }
        mx_lo = fmaxf(mx_lo, __shfl_xor_sync(0xffffffffu, mx_lo, 1));
        mx_lo = fmaxf(mx_lo, __shfl_xor_sync(0xffffffffu, mx_lo, 2));
        mx_hi = fmaxf(mx_hi, __shfl_xor_sync(0xffffffffu, mx_hi, 1));
        mx_hi = fmaxf(mx_hi, __shfl_xor_sync(0xffffffffu, mx_hi, 2));

        float mn_lo = fmaxf(m_lo, mx_lo), mn_hi = fmaxf(m_hi, mx_hi);
        float al_lo = __expf(m_lo - mn_lo), al_hi = __expf(m_hi - mn_hi);
        m_lo = mn_lo; m_hi = mn_hi;

        float rs_lo = 0.f, rs_hi = 0.f;
        uint32_t* plo = Ps + (wr + g) * PSTRIDE + 2 * tg;
        uint32_t* phi = Ps + (wr + g + 8) * PSTRIDE + 2 * tg;
#pragma unroll
        for (int ni = 0; ni < 8; ni++) {
            float p0 = __expf(sc[ni][0] - mn_lo);
            float p1 = __expf(sc[ni][1] - mn_lo);
            float p2 = __expf(sc[ni][2] - mn_hi);
            float p3 = __expf(sc[ni][3] - mn_hi);
            rs_lo += p0 + p1;
            rs_hi += p2 + p3;
            plo[ni * 8 + 0] = f2tf32(p0);
            plo[ni * 8 + 1] = f2tf32(p1);
            phi[ni * 8 + 0] = f2tf32(p2);
            phi[ni * 8 + 1] = f2tf32(p3);
        }
        rs_lo += __shfl_xor_sync(0xffffffffu, rs_lo, 1);
        rs_lo += __shfl_xor_sync(0xffffffffu, rs_lo, 2);
        rs_hi += __shfl_xor_sync(0xffffffffu, rs_hi, 1);
        rs_hi += __shfl_xor_sync(0xffffffffu, rs_hi, 2);
        l_lo = l_lo * al_lo + rs_lo;
        l_hi = l_hi * al_hi + rs_hi;

#pragma unroll
        for (int ni = 0; ni < 8; ni++) {
            o[ni][0] *= al_lo; o[ni][1] *= al_lo;
            o[ni][2] *= al_hi; o[ni][3] *= al_hi;
        }
        __syncwarp();   // P region is warp-private; order store->load

        // O += P @ V
#pragma unroll
        for (int ki = 0; ki < 8; ki++) {
            uint32_t ap[4];
            ap[0] = Ps[(wr + g) * PSTRIDE + ki * 8 + tg];
            ap[1] = Ps[(wr + g + 8) * PSTRIDE + ki * 8 + tg];
            ap[2] = Ps[(wr + g) * PSTRIDE + ki * 8 + tg + 4];
            ap[3] = Ps[(wr + g + 8) * PSTRIDE + ki * 8 + tg + 4];
#pragma unroll
            for (int ni = 0; ni < 8; ni++) {
                uint32_t b0 = Vs[(ki * 8 + tg) * VSTRIDE + ni * 8 + g];
                uint32_t b1 = Vs[(ki * 8 + tg + 4) * VSTRIDE + ni * 8 + g];
                mma_tf32(o[ni], ap, b0, b1);
            }
        }
    }

    // epilogue: normalize, write ctx [s][b][h*64+c]
    float inv_lo = 1.f / l_lo, inv_hi = 1.f / l_hi;
    int s = qs0 + wr + g;
    int cb = h * DH + 2 * tg;
#pragma unroll
    for (int ni = 0; ni < 8; ni++) {
        float2 w0 = {o[ni][0] * inv_lo, o[ni][1] * inv_lo};
        float2 w1 = {o[ni][2] * inv_hi, o[ni][3] * inv_hi};
        *(float2*)&g_ctx[(size_t)(s * BB + b) * DMOD + cb + ni * 8] = w0;
        *(float2*)&g_ctx[(size_t)((s + 8) * BB + b) * DMOD + cb + ni * 8] = w1;
    }
}

// ---------------- launch ----------------
extern "C" void kernel_launch(void* const* d_in, const int* in_sizes, int n_in,
                              void* d_out, int out_size)
{
    const float* Q  = (const float*)d_in[0];
    const float* Wq = (const float*)d_in[1];
    const float* bq = (const float*)d_in[2];
    const float* Wk = (const float*)d_in[3];
    const float* bk = (const float*)d_in[4];
    const float* Wv = (const float*)d_in[5];
    const float* bv = (const float*)d_in[6];
    const float* Wo = (const float*)d_in[7];
    const float* bo = (const float*)d_in[8];
    float* out = (float*)d_out;

    const int M = SS * BB;  // 8192
    const size_t gemm_smem = (size_t)(2 * BM * AS_STRIDE + 2 * BK * BS_STRIDE) * 4;

    pack_kernel<<<(DMOD * NQKV + 255) / 256, 256>>>(Wq, bq, Wk, bk, Wv, bv);

    {
        cudaFuncSetAttribute(tf32_gemm<1>, cudaFuncAttributeMaxDynamicSharedMemorySize,
                             (int)gemm_smem);
        dim3 grid(NQKV / BN, M / BM);
        tf32_gemm<1><<<grid, 256, gemm_smem>>>(Q, nullptr, nullptr, nullptr, M, NQKV, DMOD);
    }

    {
        size_t smem = (size_t)(64 * KSTRIDE + 64 * VSTRIDE + 128 * PSTRIDE) * 4;
        cudaFuncSetAttribute(flash_tf32, cudaFuncAttributeMaxDynamicSharedMemorySize,
                             (int)smem);
        flash_tf32<<<dim3(SS / 128, HH * BB), 256, smem>>>();
    }

    {
        cudaFuncSetAttribute(tf32_gemm<0>, cudaFuncAttributeMaxDynamicSharedMemorySize,
                             (int)gemm_smem);
        dim3 grid(DMOD / BN, M / BM);
        tf32_gemm<0><<<grid, 256, gemm_smem>>>(nullptr, Wo, bo, out, M, DMOD, DMOD);
    }
}

// round 7
// speedup vs baseline: 2.8302x; 1.0440x over previous
#include <cuda_runtime.h>
#include <math.h>
#include <stdint.h>

#define HH 16
#define BB 8
#define SS 1024
#define DMOD 1024
#define DH 64
#define NQKV 3072   // 16 heads * (64+64+64)

// ---------------- scratch (device globals; no allocation allowed) ----------------
__device__ uint32_t g_W[DMOD * NQKV];       // tf32 bits, [k][n] (k-major rows of N)
__device__ uint32_t g_Wo[DMOD * DMOD];      // tf32 bits, [k][n]
__device__ uint32_t g_Atf[SS * BB * DMOD];  // tf32 bits of input Q, [m][k]
__device__ float g_bias[NQKV];
__device__ float g_q[HH * BB * SS * DH];    // tf32-valued floats [h][b][s][c]
__device__ float g_k[HH * BB * SS * DH];
__device__ float g_v[HH * BB * SS * DH];
__device__ float g_ctx[SS * BB * DMOD];     // tf32-valued floats [s][b][h*64+v]

// ---------------- helpers ----------------
__device__ __forceinline__ uint32_t f2tf32(float x) {
    uint32_t u;
    asm("cvt.rna.tf32.f32 %0, %1;" : "=r"(u) : "f"(x));
    return u;
}

__device__ __forceinline__ uint32_t smem_u32(const void* p) {
    uint32_t a;
    asm("{ .reg .u64 t; cvta.to.shared.u64 t, %1; cvt.u32.u64 %0, t; }"
        : "=r"(a) : "l"(p));
    return a;
}

__device__ __forceinline__ void cp16(uint32_t dst, const void* src) {
    asm volatile("cp.async.cg.shared.global [%0], [%1], 16;"
                 :: "r"(dst), "l"(src) : "memory");
}
#define CP_COMMIT() asm volatile("cp.async.commit_group;" ::: "memory")
#define CP_WAIT(n)  asm volatile("cp.async.wait_group %0;" :: "n"(n) : "memory")

__device__ __forceinline__ void mma_tf32(float* d, const uint32_t* a,
                                         uint32_t b0, uint32_t b1) {
    asm volatile(
        "mma.sync.aligned.m16n8k8.row.col.f32.tf32.tf32.f32 "
        "{%0,%1,%2,%3}, {%4,%5,%6,%7}, {%8,%9}, {%0,%1,%2,%3};"
        : "+f"(d[0]), "+f"(d[1]), "+f"(d[2]), "+f"(d[3])
        : "r"(a[0]), "r"(a[1]), "r"(a[2]), "r"(a[3]), "r"(b0), "r"(b1));
}

// ---------------- pre-conversion kernels ----------------
__global__ void pack_qkv(const float* __restrict__ Wq, const float* __restrict__ bq,
                         const float* __restrict__ Wk, const float* __restrict__ bk,
                         const float* __restrict__ Wv, const float* __restrict__ bv)
{
    int idx = blockIdx.x * blockDim.x + threadIdx.x;
    if (idx >= DMOD * NQKV) return;
    int d = idx / NQKV, n = idx % NQKV;
    int h = n / 192, j = n % 192, t = j >> 6, c = j & 63;
    const float* Wsrc = (t == 0) ? Wq : (t == 1) ? Wk : Wv;
    g_W[idx] = f2tf32(Wsrc[(h * DMOD + d) * DH + c]);
    if (idx < NQKV) {
        const float* bsrc = (t == 0) ? bq : (t == 1) ? bk : bv;
        g_bias[idx] = bsrc[h * DH + c];
    }
}

__global__ void pack_wo(const float* __restrict__ Wo)
{
    int idx = blockIdx.x * blockDim.x + threadIdx.x;
    if (idx >= DMOD * DMOD) return;
    g_Wo[idx] = f2tf32(Wo[idx]);
}

__global__ void cvt_q(const float* __restrict__ Q)
{
    int idx = blockIdx.x * blockDim.x + threadIdx.x;   // float4 granularity
    float4 v = *(const float4*)(Q + idx * 4);
    uint4 u = {f2tf32(v.x), f2tf32(v.y), f2tf32(v.z), f2tf32(v.w)};
    *(uint4*)(g_Atf + idx * 4) = u;
}

// ---------------- TF32 tensor-core GEMM with cp.async pipeline ----------------
// Block tile 128x128x32; 8 warps, each 64x32 via 4x4 m16n8k8 tiles.
// A smem: [m][k] stride 36 (bank 4g+tg bijective); B smem: [k][n] stride 136 (8tg+g).
// MODE 1: A = g_Atf, B = g_W,  bias = g_bias, scatter tf32 bits into g_q/g_k/g_v
// MODE 0: A = g_ctx(tf32 bits), B = g_Wo, bias = param, C = param fp32 row-major
#define BM 128
#define BN 128
#define BK 32
#define STAGES 4
#define AS_STRIDE 36
#define BS_STRIDE 136
#define A_WORDS (BM * AS_STRIDE)            // 4608
#define B_WORDS (BK * BS_STRIDE)            // 4352
#define STG_WORDS (A_WORDS + B_WORDS)       // 8960
#define GEMM_SMEM (STAGES * STG_WORDS * 4)  // 143360 B

template <int MODE>
__global__ void __launch_bounds__(256) tf32_gemm(const float* __restrict__ biasparam,
                                                 float* __restrict__ C)
{
    constexpr int N = (MODE == 1) ? NQKV : DMOD;
    constexpr int K = DMOD;
    extern __shared__ uint32_t smem[];

    const uint32_t* Ag = (MODE == 1) ? g_Atf : (const uint32_t*)g_ctx;
    const uint32_t* Bg = (MODE == 1) ? g_W   : g_Wo;

    int tid = threadIdx.x;
    int warp = tid >> 5, lane = tid & 31;
    int wm = warp >> 2, wn = warp & 3;
    int g = lane >> 2, tg = lane & 3;
    int rowBase = blockIdx.y * BM;
    int colBase = blockIdx.x * BN;

    uint32_t sbase = smem_u32(smem);
    // per-thread load slots (4 A chunks + 4 B chunks per stage)
    int arow = tid >> 1, aseg = (tid & 1) << 2;          // 2 chunks/row? no:
    // A: 1024 chunks of 16B (128 rows x 8 segs). chunk c: row=c>>3, seg=c&7
    // B: 1024 chunks (32 rows x 32 segs). chunk c: row=c>>5, seg=c&31
    (void)arow; (void)aseg;

    float acc[4][4][4];
#pragma unroll
    for (int mi = 0; mi < 4; mi++)
#pragma unroll
        for (int ni = 0; ni < 4; ni++)
#pragma unroll
            for (int r = 0; r < 4; r++) acc[mi][ni][r] = 0.f;

    const int ntiles = K / BK;   // 32

    auto load_stage = [&](int kt) {
        int st = kt & (STAGES - 1);
        uint32_t sa = sbase + st * STG_WORDS * 4;
        uint32_t sb = sa + A_WORDS * 4;
        int k0 = kt * BK;
#pragma unroll
        for (int i = 0; i < 4; i++) {
            int c = tid + 256 * i;
            int row = c >> 3, seg = c & 7;
            cp16(sa + (row * AS_STRIDE + seg * 4) * 4,
                 Ag + (size_t)(rowBase + row) * K + k0 + seg * 4);
        }
#pragma unroll
        for (int i = 0; i < 4; i++) {
            int c = tid + 256 * i;
            int row = c >> 5, seg = c & 31;
            cp16(sb + (row * BS_STRIDE + seg * 4) * 4,
                 Bg + (size_t)(k0 + row) * N + colBase + seg * 4);
        }
        CP_COMMIT();
    };

    // prologue: stages 0..STAGES-2
#pragma unroll
    for (int kt = 0; kt < STAGES - 1; kt++) load_stage(kt);

    for (int kt = 0; kt < ntiles; kt++) {
        CP_WAIT(STAGES - 2);
        __syncthreads();
        if (kt + STAGES - 1 < ntiles) load_stage(kt + STAGES - 1);
        else CP_COMMIT();

        int st = kt & (STAGES - 1);
        const uint32_t* as = smem + st * STG_WORDS;
        const uint32_t* bs = as + A_WORDS;

#pragma unroll
        for (int ks = 0; ks < 4; ks++) {
            uint32_t afrag[4][4], bfrag[4][2];
#pragma unroll
            for (int mi = 0; mi < 4; mi++) {
                int rr = wm * 64 + mi * 16;
                const uint32_t* p  = as + (rr + g) * AS_STRIDE + ks * 8 + tg;
                const uint32_t* p2 = p + 8 * AS_STRIDE;
                afrag[mi][0] = p[0];
                afrag[mi][1] = p2[0];
                afrag[mi][2] = p[4];
                afrag[mi][3] = p2[4];
            }
#pragma unroll
            for (int ni = 0; ni < 4; ni++) {
                int nn = wn * 32 + ni * 8 + g;
                bfrag[ni][0] = bs[(ks * 8 + tg) * BS_STRIDE + nn];
                bfrag[ni][1] = bs[(ks * 8 + tg + 4) * BS_STRIDE + nn];
            }
#pragma unroll
            for (int mi = 0; mi < 4; mi++)
#pragma unroll
                for (int ni = 0; ni < 4; ni++)
                    mma_tf32(acc[mi][ni], afrag[mi], bfrag[ni][0], bfrag[ni][1]);
        }
    }

    // epilogue: thread owns (g, tg*2) / (+8, +1) quads per mma tile
#pragma unroll
    for (int mi = 0; mi < 4; mi++) {
#pragma unroll
        for (int ni = 0; ni < 4; ni++) {
            int r0 = rowBase + wm * 64 + mi * 16 + g;
            int cn = colBase + wn * 32 + ni * 8 + tg * 2;
            if (MODE == 0) {
                float2 bv = *(const float2*)&biasparam[cn];
                float2 o0 = {acc[mi][ni][0] + bv.x, acc[mi][ni][1] + bv.y};
                float2 o1 = {acc[mi][ni][2] + bv.x, acc[mi][ni][3] + bv.y};
                *(float2*)&C[(size_t)r0 * N + cn] = o0;
                *(float2*)&C[(size_t)(r0 + 8) * N + cn] = o1;
            } else {
#pragma unroll
                for (int e = 0; e < 4; e++) {
                    int r = r0 + (e >> 1) * 8;
                    int n = cn + (e & 1);
                    int s = r >> 3, b = r & 7;
                    int h = n / 192, jj = n % 192, ty = jj >> 6, c = jj & 63;
                    float val = acc[mi][ni][e] + g_bias[n];
                    float* bufp = (ty == 0) ? g_q : (ty == 1) ? g_k : g_v;
                    bufp[((h * BB + b) * SS + s) * DH + c] =
                        __uint_as_float(f2tf32(val));   // store tf32 bits
                }
            }
        }
    }
}

// ---------------- TF32 mma.sync flash attention ----------------
// q/k/v arrive as tf32-valued floats: K/V smem staging is a raw copy,
// Q scaling by 0.125 (power of two) keeps values exactly tf32.
#define KSTRIDE 68
#define VSTRIDE 72
#define PSTRIDE 68

__global__ void __launch_bounds__(256) flash_tf32()
{
    extern __shared__ uint32_t sm[];
    uint32_t* Ks = sm;
    uint32_t* Vs = Ks + 64 * KSTRIDE;
    uint32_t* Ps = Vs + 64 * VSTRIDE;

    int tid = threadIdx.x;
    int warp = tid >> 5, lane = tid & 31;
    int g = lane >> 2, tg = lane & 3;
    int qx = blockIdx.x;
    int hb = blockIdx.y;
    int h = hb >> 3, b = hb & 7;
    int qs0 = qx * 128;
    int wr = warp * 16;

    const float* qg  = g_q + ((size_t)(h * BB + b) * SS + qs0) * DH;
    const uint32_t* kg0 = (const uint32_t*)g_k + (size_t)(h * BB + b) * SS * DH;
    const uint32_t* vg0 = (const uint32_t*)g_v + (size_t)(h * BB + b) * SS * DH;

    uint32_t aq[8][4];
#pragma unroll
    for (int ki = 0; ki < 8; ki++) {
        const float* qp = qg + (wr + g) * DH + ki * 8 + tg;
        aq[ki][0] = __float_as_uint(qp[0] * 0.125f);
        aq[ki][1] = __float_as_uint(qp[8 * DH] * 0.125f);
        aq[ki][2] = __float_as_uint(qp[4] * 0.125f);
        aq[ki][3] = __float_as_uint(qp[8 * DH + 4] * 0.125f);
    }

    float o[8][4];
#pragma unroll
    for (int ni = 0; ni < 8; ni++)
#pragma unroll
        for (int e = 0; e < 4; e++) o[ni][e] = 0.f;
    float m_lo = -INFINITY, m_hi = -INFINITY, l_lo = 0.f, l_hi = 0.f;

    const int nkt = 2 * (qx + 1);
    for (int kt = 0; kt < nkt; kt++) {
        const uint32_t* kg = kg0 + (size_t)kt * 64 * DH;
        const uint32_t* vg = vg0 + (size_t)kt * 64 * DH;
        __syncthreads();
#pragma unroll
        for (int t = 0; t < 4; t++) {
            int f = tid + t * 256;
            int row = f >> 4, c4 = (f & 15) << 2;
            uint4 kv = *(const uint4*)(kg + row * DH + c4);
            uint32_t* kp = Ks + row * KSTRIDE + c4;
            kp[0] = kv.x; kp[1] = kv.y; kp[2] = kv.z; kp[3] = kv.w;
            uint4 vv = *(const uint4*)(vg + row * DH + c4);
            uint32_t* vp = Vs + row * VSTRIDE + c4;
            vp[0] = vv.x; vp[1] = vv.y; vp[2] = vv.z; vp[3] = vv.w;
        }
        __syncthreads();

        float sc[8][4];
#pragma unroll
        for (int ni = 0; ni < 8; ni++)
#pragma unroll
            for (int e = 0; e < 4; e++) sc[ni][e] = 0.f;
#pragma unroll
        for (int ki = 0; ki < 8; ki++) {
#pragma unroll
            for (int ni = 0; ni < 8; ni++) {
                const uint32_t* kb = Ks + (ni * 8 + g) * KSTRIDE + ki * 8 + tg;
                mma_tf32(sc[ni], aq[ki], kb[0], kb[4]);
            }
        }

        if (kt * 64 + 63 > qs0 + wr) {
            int rlo = qs0 + wr + g, rhi = rlo + 8;
#pragma unroll
            for (int ni = 0; ni < 8; ni++) {
                int col = kt * 64 + ni * 8 + 2 * tg;
                if (col     > rlo) sc[ni][0] = -1e30f;
                if (col + 1 > rlo) sc[ni][1] = -1e30f;
                if (col     > rhi) sc[ni][2] = -1e30f;
                if (col + 1 > rhi) sc[ni][3] = -1e30f;
            }
        }

        float mx_lo = -1e30f, mx_hi = -1e30f;
#pragma unroll
        for (int ni = 0; ni < 8; ni++) {
            mx_lo = fmaxf(mx_lo, fmaxf(sc[ni][0], sc[ni][1]));
            mx_hi = fmaxf(mx_hi, fmaxf(sc[ni][2], sc[ni][3]));
        }
        mx_lo = fmaxf(mx_lo, __shfl_xor_sync(0xffffffffu, mx_lo, 1));
        mx_lo = fmaxf(mx_lo, __shfl_xor_sync(0xffffffffu, mx_lo, 2));
        mx_hi = fmaxf(mx_hi, __shfl_xor_sync(0xffffffffu, mx_hi, 1));
        mx_hi = fmaxf(mx_hi, __shfl_xor_sync(0xffffffffu, mx_hi, 2));

        float mn_lo = fmaxf(m_lo, mx_lo), mn_hi = fmaxf(m_hi, mx_hi);
        float al_lo = __expf(m_lo - mn_lo), al_hi = __expf(m_hi - mn_hi);
        m_lo = mn_lo; m_hi = mn_hi;

        float rs_lo = 0.f, rs_hi = 0.f;
        uint32_t* plo = Ps + (wr + g) * PSTRIDE + 2 * tg;
        uint32_t* phi = Ps + (wr + g + 8) * PSTRIDE + 2 * tg;
#pragma unroll
        for (int ni = 0; ni < 8; ni++) {
            float p0 = __expf(sc[ni][0] - mn_lo);
            float p1 = __expf(sc[ni][1] - mn_lo);
            float p2 = __expf(sc[ni][2] - mn_hi);
            float p3 = __expf(sc[ni][3] - mn_hi);
            rs_lo += p0 + p1;
            rs_hi += p2 + p3;
            plo[ni * 8 + 0] = f2tf32(p0);
            plo[ni * 8 + 1] = f2tf32(p1);
            phi[ni * 8 + 0] = f2tf32(p2);
            phi[ni * 8 + 1] = f2tf32(p3);
        }
        rs_lo += __shfl_xor_sync(0xffffffffu, rs_lo, 1);
        rs_lo += __shfl_xor_sync(0xffffffffu, rs_lo, 2);
        rs_hi += __shfl_xor_sync(0xffffffffu, rs_hi, 1);
        rs_hi += __shfl_xor_sync(0xffffffffu, rs_hi, 2);
        l_lo = l_lo * al_lo + rs_lo;
        l_hi = l_hi * al_hi + rs_hi;

#pragma unroll
        for (int ni = 0; ni < 8; ni++) {
            o[ni][0] *= al_lo; o[ni][1] *= al_lo;
            o[ni][2] *= al_hi; o[ni][3] *= al_hi;
        }
        __syncwarp();

#pragma unroll
        for (int ki = 0; ki < 8; ki++) {
            uint32_t ap[4];
            ap[0] = Ps[(wr + g) * PSTRIDE + ki * 8 + tg];
            ap[1] = Ps[(wr + g + 8) * PSTRIDE + ki * 8 + tg];
            ap[2] = Ps[(wr + g) * PSTRIDE + ki * 8 + tg + 4];
            ap[3] = Ps[(wr + g + 8) * PSTRIDE + ki * 8 + tg + 4];
#pragma unroll
            for (int ni = 0; ni < 8; ni++) {
                uint32_t b0 = Vs[(ki * 8 + tg) * VSTRIDE + ni * 8 + g];
                uint32_t b1 = Vs[(ki * 8 + tg + 4) * VSTRIDE + ni * 8 + g];
                mma_tf32(o[ni], ap, b0, b1);
            }
        }
    }

    // epilogue: normalize, write ctx as tf32 bits
    float inv_lo = 1.f / l_lo, inv_hi = 1.f / l_hi;
    int s = qs0 + wr + g;
    int cb = h * DH + 2 * tg;
    uint32_t* ctx = (uint32_t*)g_ctx;
#pragma unroll
    for (int ni = 0; ni < 8; ni++) {
        uint2 w0 = {f2tf32(o[ni][0] * inv_lo), f2tf32(o[ni][1] * inv_lo)};
        uint2 w1 = {f2tf32(o[ni][2] * inv_hi), f2tf32(o[ni][3] * inv_hi)};
        *(uint2*)&ctx[(size_t)(s * BB + b) * DMOD + cb + ni * 8] = w0;
        *(uint2*)&ctx[(size_t)((s + 8) * BB + b) * DMOD + cb + ni * 8] = w1;
    }
}

// ---------------- launch ----------------
extern "C" void kernel_launch(void* const* d_in, const int* in_sizes, int n_in,
                              void* d_out, int out_size)
{
    const float* Q  = (const float*)d_in[0];
    const float* Wq = (const float*)d_in[1];
    const float* bq = (const float*)d_in[2];
    const float* Wk = (const float*)d_in[3];
    const float* bk = (const float*)d_in[4];
    const float* Wv = (const float*)d_in[5];
    const float* bv = (const float*)d_in[6];
    const float* Wo = (const float*)d_in[7];
    const float* bo = (const float*)d_in[8];
    float* out = (float*)d_out;

    const int M = SS * BB;  // 8192

    // 1) pre-convert weights + input to tf32 bits
    pack_qkv<<<(DMOD * NQKV + 255) / 256, 256>>>(Wq, bq, Wk, bk, Wv, bv);
    pack_wo<<<(DMOD * DMOD + 255) / 256, 256>>>(Wo);
    cvt_q<<<(M * DMOD / 4 + 255) / 256, 256>>>(Q);

    // 2) QKV projection: (8192x1024) @ (1024x3072) -> q/k/v (tf32 bits)
    {
        cudaFuncSetAttribute(tf32_gemm<1>, cudaFuncAttributeMaxDynamicSharedMemorySize,
                             GEMM_SMEM);
        dim3 grid(NQKV / BN, M / BM);
        tf32_gemm<1><<<grid, 256, GEMM_SMEM>>>(nullptr, nullptr);
    }

    // 3) causal flash attention -> g_ctx (tf32 bits)
    {
        size_t smem = (size_t)(64 * KSTRIDE + 64 * VSTRIDE + 128 * PSTRIDE) * 4;
        cudaFuncSetAttribute(flash_tf32, cudaFuncAttributeMaxDynamicSharedMemorySize,
                             (int)smem);
        flash_tf32<<<dim3(SS / 128, HH * BB), 256, smem>>>();
    }

    // 4) output projection: ctx (8192x1024) @ Wo + bo -> out (fp32)
    {
        cudaFuncSetAttribute(tf32_gemm<0>, cudaFuncAttributeMaxDynamicSharedMemorySize,
                             GEMM_SMEM);
        dim3 grid(DMOD / BN, M / BM);
        tf32_gemm<0><<<grid, 256, GEMM_SMEM>>>(bo, out);
    }
}

// round 8
// speedup vs baseline: 3.1804x; 1.1237x over previous
#include <cuda_runtime.h>
#include <math.h>
#include <stdint.h>

#define HH 16
#define BB 8
#define SS 1024
#define DMOD 1024
#define DH 64
#define NQKV 3072   // 16 heads * (64+64+64)

// ---------------- scratch (device globals; no allocation allowed) ----------------
__device__ uint32_t g_W[DMOD * NQKV];       // tf32 bits, [k][n]
__device__ uint32_t g_Wo[DMOD * DMOD];      // tf32 bits, [k][n]
__device__ uint32_t g_Atf[SS * BB * DMOD];  // tf32 bits of input Q, [m][k]
__device__ float g_bias[NQKV];
__device__ float g_q[HH * BB * SS * DH];    // tf32-valued floats [h][b][s][c]
__device__ float g_k[HH * BB * SS * DH];
__device__ float g_v[HH * BB * SS * DH];
__device__ float g_ctx[SS * BB * DMOD];     // tf32-valued floats [s][b][h*64+v]

// ---------------- helpers ----------------
__device__ __forceinline__ uint32_t f2tf32(float x) {
    uint32_t u;
    asm("cvt.rna.tf32.f32 %0, %1;" : "=r"(u) : "f"(x));
    return u;
}

__device__ __forceinline__ uint32_t smem_u32(const void* p) {
    uint32_t a;
    asm("{ .reg .u64 t; cvta.to.shared.u64 t, %1; cvt.u32.u64 %0, t; }"
        : "=r"(a) : "l"(p));
    return a;
}

__device__ __forceinline__ void cp16(uint32_t dst, const void* src) {
    asm volatile("cp.async.cg.shared.global [%0], [%1], 16;"
                 :: "r"(dst), "l"(src) : "memory");
}
#define CP_COMMIT() asm volatile("cp.async.commit_group;" ::: "memory")
#define CP_WAIT(n)  asm volatile("cp.async.wait_group %0;" :: "n"(n) : "memory")

__device__ __forceinline__ void mma_tf32(float* d, const uint32_t* a,
                                         uint32_t b0, uint32_t b1) {
    asm volatile(
        "mma.sync.aligned.m16n8k8.row.col.f32.tf32.tf32.f32 "
        "{%0,%1,%2,%3}, {%4,%5,%6,%7}, {%8,%9}, {%0,%1,%2,%3};"
        : "+f"(d[0]), "+f"(d[1]), "+f"(d[2]), "+f"(d[3])
        : "r"(a[0]), "r"(a[1]), "r"(a[2]), "r"(a[3]), "r"(b0), "r"(b1));
}

// ---------------- pre-conversion kernels ----------------
__global__ void pack_qkv(const float* __restrict__ Wq, const float* __restrict__ bq,
                         const float* __restrict__ Wk, const float* __restrict__ bk,
                         const float* __restrict__ Wv, const float* __restrict__ bv)
{
    int idx = blockIdx.x * blockDim.x + threadIdx.x;
    if (idx >= DMOD * NQKV) return;
    int d = idx / NQKV, n = idx % NQKV;
    int h = n / 192, j = n % 192, t = j >> 6, c = j & 63;
    const float* Wsrc = (t == 0) ? Wq : (t == 1) ? Wk : Wv;
    g_W[idx] = f2tf32(Wsrc[(h * DMOD + d) * DH + c]);
    if (idx < NQKV) {
        const float* bsrc = (t == 0) ? bq : (t == 1) ? bk : bv;
        g_bias[idx] = bsrc[h * DH + c];
    }
}

__global__ void pack_wo(const float* __restrict__ Wo)
{
    int idx = blockIdx.x * blockDim.x + threadIdx.x;
    if (idx >= DMOD * DMOD) return;
    g_Wo[idx] = f2tf32(Wo[idx]);
}

__global__ void cvt_q(const float* __restrict__ Q)
{
    int idx = blockIdx.x * blockDim.x + threadIdx.x;   // float4 granularity
    float4 v = *(const float4*)(Q + idx * 4);
    uint4 u = {f2tf32(v.x), f2tf32(v.y), f2tf32(v.z), f2tf32(v.w)};
    *(uint4*)(g_Atf + idx * 4) = u;
}

// ---------------- TF32 tensor-core GEMM with cp.async pipeline ----------------
// Block tile 128x128x32; 8 warps, each 64x32 via 4x4 m16n8k8 tiles.
// STAGES=3 (105KB smem) + __launch_bounds__(256,2) -> 2 CTAs/SM, 16 warps.
#define BM 128
#define BN 128
#define BK 32
#define STAGES 3
#define AS_STRIDE 36
#define BS_STRIDE 136
#define A_WORDS (BM * AS_STRIDE)            // 4608
#define B_WORDS (BK * BS_STRIDE)            // 4352
#define STG_WORDS (A_WORDS + B_WORDS)       // 8960
#define GEMM_SMEM (STAGES * STG_WORDS * 4)  // 107520 B

template <int MODE>
__global__ void __launch_bounds__(256, 2) tf32_gemm(const float* __restrict__ biasparam,
                                                    float* __restrict__ C)
{
    constexpr int N = (MODE == 1) ? NQKV : DMOD;
    constexpr int K = DMOD;
    extern __shared__ uint32_t smem[];

    const uint32_t* Ag = (MODE == 1) ? g_Atf : (const uint32_t*)g_ctx;
    const uint32_t* Bg = (MODE == 1) ? g_W   : g_Wo;

    int tid = threadIdx.x;
    int warp = tid >> 5, lane = tid & 31;
    int wm = warp >> 2, wn = warp & 3;
    int g = lane >> 2, tg = lane & 3;
    int rowBase = blockIdx.y * BM;
    int colBase = blockIdx.x * BN;

    uint32_t sbase = smem_u32(smem);

    float acc[4][4][4];
#pragma unroll
    for (int mi = 0; mi < 4; mi++)
#pragma unroll
        for (int ni = 0; ni < 4; ni++)
#pragma unroll
            for (int r = 0; r < 4; r++) acc[mi][ni][r] = 0.f;

    const int ntiles = K / BK;   // 32

    auto load_stage = [&](int kt) {
        int st = kt % STAGES;
        uint32_t sa = sbase + st * STG_WORDS * 4;
        uint32_t sb = sa + A_WORDS * 4;
        int k0 = kt * BK;
#pragma unroll
        for (int i = 0; i < 4; i++) {
            int c = tid + 256 * i;
            int row = c >> 3, seg = c & 7;
            cp16(sa + (row * AS_STRIDE + seg * 4) * 4,
                 Ag + (size_t)(rowBase + row) * K + k0 + seg * 4);
        }
#pragma unroll
        for (int i = 0; i < 4; i++) {
            int c = tid + 256 * i;
            int row = c >> 5, seg = c & 31;
            cp16(sb + (row * BS_STRIDE + seg * 4) * 4,
                 Bg + (size_t)(k0 + row) * N + colBase + seg * 4);
        }
        CP_COMMIT();
    };

    // prologue: stages 0..STAGES-2
#pragma unroll
    for (int kt = 0; kt < STAGES - 1; kt++) load_stage(kt);

    for (int kt = 0; kt < ntiles; kt++) {
        CP_WAIT(STAGES - 2);
        __syncthreads();
        if (kt + STAGES - 1 < ntiles) load_stage(kt + STAGES - 1);
        else CP_COMMIT();

        int st = kt % STAGES;
        const uint32_t* as = smem + st * STG_WORDS;
        const uint32_t* bs = as + A_WORDS;

#pragma unroll
        for (int ks = 0; ks < 4; ks++) {
            uint32_t afrag[4][4], bfrag[4][2];
#pragma unroll
            for (int mi = 0; mi < 4; mi++) {
                int rr = wm * 64 + mi * 16;
                const uint32_t* p  = as + (rr + g) * AS_STRIDE + ks * 8 + tg;
                const uint32_t* p2 = p + 8 * AS_STRIDE;
                afrag[mi][0] = p[0];
                afrag[mi][1] = p2[0];
                afrag[mi][2] = p[4];
                afrag[mi][3] = p2[4];
            }
#pragma unroll
            for (int ni = 0; ni < 4; ni++) {
                int nn = wn * 32 + ni * 8 + g;
                bfrag[ni][0] = bs[(ks * 8 + tg) * BS_STRIDE + nn];
                bfrag[ni][1] = bs[(ks * 8 + tg + 4) * BS_STRIDE + nn];
            }
#pragma unroll
            for (int mi = 0; mi < 4; mi++)
#pragma unroll
                for (int ni = 0; ni < 4; ni++)
                    mma_tf32(acc[mi][ni], afrag[mi], bfrag[ni][0], bfrag[ni][1]);
        }
    }

    // epilogue
#pragma unroll
    for (int mi = 0; mi < 4; mi++) {
#pragma unroll
        for (int ni = 0; ni < 4; ni++) {
            int r0 = rowBase + wm * 64 + mi * 16 + g;
            int cn = colBase + wn * 32 + ni * 8 + tg * 2;
            if (MODE == 0) {
                float2 bv = *(const float2*)&biasparam[cn];
                float2 o0 = {acc[mi][ni][0] + bv.x, acc[mi][ni][1] + bv.y};
                float2 o1 = {acc[mi][ni][2] + bv.x, acc[mi][ni][3] + bv.y};
                *(float2*)&C[(size_t)r0 * N + cn] = o0;
                *(float2*)&C[(size_t)(r0 + 8) * N + cn] = o1;
            } else {
#pragma unroll
                for (int e = 0; e < 4; e++) {
                    int r = r0 + (e >> 1) * 8;
                    int n = cn + (e & 1);
                    int s = r >> 3, b = r & 7;
                    int h = n / 192, jj = n % 192, ty = jj >> 6, c = jj & 63;
                    float val = acc[mi][ni][e] + g_bias[n];
                    float* bufp = (ty == 0) ? g_q : (ty == 1) ? g_k : g_v;
                    bufp[((h * BB + b) * SS + s) * DH + c] =
                        __uint_as_float(f2tf32(val));   // store tf32 bits
                }
            }
        }
    }
}

// ---------------- TF32 mma.sync flash attention (unchanged from R7) ----------------
#define KSTRIDE 68
#define VSTRIDE 72
#define PSTRIDE 68

__global__ void __launch_bounds__(256) flash_tf32()
{
    extern __shared__ uint32_t sm[];
    uint32_t* Ks = sm;
    uint32_t* Vs = Ks + 64 * KSTRIDE;
    uint32_t* Ps = Vs + 64 * VSTRIDE;

    int tid = threadIdx.x;
    int warp = tid >> 5, lane = tid & 31;
    int g = lane >> 2, tg = lane & 3;
    int qx = blockIdx.x;
    int hb = blockIdx.y;
    int h = hb >> 3, b = hb & 7;
    int qs0 = qx * 128;
    int wr = warp * 16;

    const float* qg  = g_q + ((size_t)(h * BB + b) * SS + qs0) * DH;
    const uint32_t* kg0 = (const uint32_t*)g_k + (size_t)(h * BB + b) * SS * DH;
    const uint32_t* vg0 = (const uint32_t*)g_v + (size_t)(h * BB + b) * SS * DH;

    uint32_t aq[8][4];
#pragma unroll
    for (int ki = 0; ki < 8; ki++) {
        const float* qp = qg + (wr + g) * DH + ki * 8 + tg;
        aq[ki][0] = __float_as_uint(qp[0] * 0.125f);
        aq[ki][1] = __float_as_uint(qp[8 * DH] * 0.125f);
        aq[ki][2] = __float_as_uint(qp[4] * 0.125f);
        aq[ki][3] = __float_as_uint(qp[8 * DH + 4] * 0.125f);
    }

    float o[8][4];
#pragma unroll
    for (int ni = 0; ni < 8; ni++)
#pragma unroll
        for (int e = 0; e < 4; e++) o[ni][e] = 0.f;
    float m_lo = -INFINITY, m_hi = -INFINITY, l_lo = 0.f, l_hi = 0.f;

    const int nkt = 2 * (qx + 1);
    for (int kt = 0; kt < nkt; kt++) {
        const uint32_t* kg = kg0 + (size_t)kt * 64 * DH;
        const uint32_t* vg = vg0 + (size_t)kt * 64 * DH;
        __syncthreads();
#pragma unroll
        for (int t = 0; t < 4; t++) {
            int f = tid + t * 256;
            int row = f >> 4, c4 = (f & 15) << 2;
            uint4 kv = *(const uint4*)(kg + row * DH + c4);
            uint32_t* kp = Ks + row * KSTRIDE + c4;
            kp[0] = kv.x; kp[1] = kv.y; kp[2] = kv.z; kp[3] = kv.w;
            uint4 vv = *(const uint4*)(vg + row * DH + c4);
            uint32_t* vp = Vs + row * VSTRIDE + c4;
            vp[0] = vv.x; vp[1] = vv.y; vp[2] = vv.z; vp[3] = vv.w;
        }
        __syncthreads();

        float sc[8][4];
#pragma unroll
        for (int ni = 0; ni < 8; ni++)
#pragma unroll
            for (int e = 0; e < 4; e++) sc[ni][e] = 0.f;
#pragma unroll
        for (int ki = 0; ki < 8; ki++) {
#pragma unroll
            for (int ni = 0; ni < 8; ni++) {
                const uint32_t* kb = Ks + (ni * 8 + g) * KSTRIDE + ki * 8 + tg;
                mma_tf32(sc[ni], aq[ki], kb[0], kb[4]);
            }
        }

        if (kt * 64 + 63 > qs0 + wr) {
            int rlo = qs0 + wr + g, rhi = rlo + 8;
#pragma unroll
            for (int ni = 0; ni < 8; ni++) {
                int col = kt * 64 + ni * 8 + 2 * tg;
                if (col     > rlo) sc[ni][0] = -1e30f;
                if (col + 1 > rlo) sc[ni][1] = -1e30f;
                if (col     > rhi) sc[ni][2] = -1e30f;
                if (col + 1 > rhi) sc[ni][3] = -1e30f;
            }
        }

        float mx_lo = -1e30f, mx_hi = -1e30f;
#pragma unroll
        for (int ni = 0; ni < 8; ni++) {
            mx_lo = fmaxf(mx_lo, fmaxf(sc[ni][0], sc[ni][1]));
            mx_hi = fmaxf(mx_hi, fmaxf(sc[ni][2], sc[ni][3]));
        }
        mx_lo = fmaxf(mx_lo, __shfl_xor_sync(0xffffffffu, mx_lo, 1));
        mx_lo = fmaxf(mx_lo, __shfl_xor_sync(0xffffffffu, mx_lo, 2));
        mx_hi = fmaxf(mx_hi, __shfl_xor_sync(0xffffffffu, mx_hi, 1));
        mx_hi = fmaxf(mx_hi, __shfl_xor_sync(0xffffffffu, mx_hi, 2));

        float mn_lo = fmaxf(m_lo, mx_lo), mn_hi = fmaxf(m_hi, mx_hi);
        float al_lo = __expf(m_lo - mn_lo), al_hi = __expf(m_hi - mn_hi);
        m_lo = mn_lo; m_hi = mn_hi;

        float rs_lo = 0.f, rs_hi = 0.f;
        uint32_t* plo = Ps + (wr + g) * PSTRIDE + 2 * tg;
        uint32_t* phi = Ps + (wr + g + 8) * PSTRIDE + 2 * tg;
#pragma unroll
        for (int ni = 0; ni < 8; ni++) {
            float p0 = __expf(sc[ni][0] - mn_lo);
            float p1 = __expf(sc[ni][1] - mn_lo);
            float p2 = __expf(sc[ni][2] - mn_hi);
            float p3 = __expf(sc[ni][3] - mn_hi);
            rs_lo += p0 + p1;
            rs_hi += p2 + p3;
            plo[ni * 8 + 0] = f2tf32(p0);
            plo[ni * 8 + 1] = f2tf32(p1);
            phi[ni * 8 + 0] = f2tf32(p2);
            phi[ni * 8 + 1] = f2tf32(p3);
        }
        rs_lo += __shfl_xor_sync(0xffffffffu, rs_lo, 1);
        rs_lo += __shfl_xor_sync(0xffffffffu, rs_lo, 2);
        rs_hi += __shfl_xor_sync(0xffffffffu, rs_hi, 1);
        rs_hi += __shfl_xor_sync(0xffffffffu, rs_hi, 2);
        l_lo = l_lo * al_lo + rs_lo;
        l_hi = l_hi * al_hi + rs_hi;

#pragma unroll
        for (int ni = 0; ni < 8; ni++) {
            o[ni][0] *= al_lo; o[ni][1] *= al_lo;
            o[ni][2] *= al_hi; o[ni][3] *= al_hi;
        }
        __syncwarp();

#pragma unroll
        for (int ki = 0; ki < 8; ki++) {
            uint32_t ap[4];
            ap[0] = Ps[(wr + g) * PSTRIDE + ki * 8 + tg];
            ap[1] = Ps[(wr + g + 8) * PSTRIDE + ki * 8 + tg];
            ap[2] = Ps[(wr + g) * PSTRIDE + ki * 8 + tg + 4];
            ap[3] = Ps[(wr + g + 8) * PSTRIDE + ki * 8 + tg + 4];
#pragma unroll
            for (int ni = 0; ni < 8; ni++) {
                uint32_t b0 = Vs[(ki * 8 + tg) * VSTRIDE + ni * 8 + g];
                uint32_t b1 = Vs[(ki * 8 + tg + 4) * VSTRIDE + ni * 8 + g];
                mma_tf32(o[ni], ap, b0, b1);
            }
        }
    }

    float inv_lo = 1.f / l_lo, inv_hi = 1.f / l_hi;
    int s = qs0 + wr + g;
    int cb = h * DH + 2 * tg;
    uint32_t* ctx = (uint32_t*)g_ctx;
#pragma unroll
    for (int ni = 0; ni < 8; ni++) {
        uint2 w0 = {f2tf32(o[ni][0] * inv_lo), f2tf32(o[ni][1] * inv_lo)};
        uint2 w1 = {f2tf32(o[ni][2] * inv_hi), f2tf32(o[ni][3] * inv_hi)};
        *(uint2*)&ctx[(size_t)(s * BB + b) * DMOD + cb + ni * 8] = w0;
        *(uint2*)&ctx[(size_t)((s + 8) * BB + b) * DMOD + cb + ni * 8] = w1;
    }
}

// ---------------- launch ----------------
extern "C" void kernel_launch(void* const* d_in, const int* in_sizes, int n_in,
                              void* d_out, int out_size)
{
    const float* Q  = (const float*)d_in[0];
    const float* Wq = (const float*)d_in[1];
    const float* bq = (const float*)d_in[2];
    const float* Wk = (const float*)d_in[3];
    const float* bk = (const float*)d_in[4];
    const float* Wv = (const float*)d_in[5];
    const float* bv = (const float*)d_in[6];
    const float* Wo = (const float*)d_in[7];
    const float* bo = (const float*)d_in[8];
    float* out = (float*)d_out;

    const int M = SS * BB;  // 8192

    // 1) pre-convert weights + input to tf32 bits
    pack_qkv<<<(DMOD * NQKV + 255) / 256, 256>>>(Wq, bq, Wk, bk, Wv, bv);
    pack_wo<<<(DMOD * DMOD + 255) / 256, 256>>>(Wo);
    cvt_q<<<(M * DMOD / 4 + 255) / 256, 256>>>(Q);

    // 2) QKV projection: (8192x1024) @ (1024x3072) -> q/k/v (tf32 bits)
    {
        cudaFuncSetAttribute(tf32_gemm<1>, cudaFuncAttributeMaxDynamicSharedMemorySize,
                             GEMM_SMEM);
        dim3 grid(NQKV / BN, M / BM);
        tf32_gemm<1><<<grid, 256, GEMM_SMEM>>>(nullptr, nullptr);
    }

    // 3) causal flash attention -> g_ctx (tf32 bits)
    {
        size_t smem = (size_t)(64 * KSTRIDE + 64 * VSTRIDE + 128 * PSTRIDE) * 4;
        cudaFuncSetAttribute(flash_tf32, cudaFuncAttributeMaxDynamicSharedMemorySize,
                             (int)smem);
        flash_tf32<<<dim3(SS / 128, HH * BB), 256, smem>>>();
    }

    // 4) output projection: ctx (8192x1024) @ Wo + bo -> out (fp32)
    {
        cudaFuncSetAttribute(tf32_gemm<0>, cudaFuncAttributeMaxDynamicSharedMemorySize,
                             GEMM_SMEM);
        dim3 grid(DMOD / BN, M / BM);
        tf32_gemm<0><<<grid, 256, GEMM_SMEM>>>(bo, out);
    }
}

// round 9
// speedup vs baseline: 3.2775x; 1.0305x over previous
#include <cuda_runtime.h>
#include <math.h>
#include <stdint.h>

#define HH 16
#define BB 8
#define SS 1024
#define DMOD 1024
#define DH 64
#define NQKV 3072   // 16 heads * (64+64+64)

// ---------------- scratch (device globals; no allocation allowed) ----------------
__device__ uint32_t g_W[NQKV * DMOD];       // tf32 bits, n-major [n][k]
__device__ uint32_t g_Wo[DMOD * DMOD];      // tf32 bits, n-major [n][k]
__device__ uint32_t g_Atf[SS * BB * DMOD];  // tf32 bits of input Q, [m][k]
__device__ float g_bias[NQKV];
__device__ float g_q[HH * BB * SS * DH];    // tf32-valued floats [h][b][s][c]
__device__ float g_k[HH * BB * SS * DH];
__device__ float g_v[HH * BB * SS * DH];
__device__ float g_ctx[SS * BB * DMOD];     // tf32-valued floats [s][b][h*64+v]

// ---------------- helpers ----------------
__device__ __forceinline__ uint32_t f2tf32(float x) {
    uint32_t u;
    asm("cvt.rna.tf32.f32 %0, %1;" : "=r"(u) : "f"(x));
    return u;
}

__device__ __forceinline__ uint32_t smem_u32(const void* p) {
    uint32_t a;
    asm("{ .reg .u64 t; cvta.to.shared.u64 t, %1; cvt.u32.u64 %0, t; }"
        : "=r"(a) : "l"(p));
    return a;
}

__device__ __forceinline__ void cp16(uint32_t dst, const void* src) {
    asm volatile("cp.async.cg.shared.global [%0], [%1], 16;"
                 :: "r"(dst), "l"(src) : "memory");
}
#define CP_COMMIT() asm volatile("cp.async.commit_group;" ::: "memory")
#define CP_WAIT(n)  asm volatile("cp.async.wait_group %0;" :: "n"(n) : "memory")

__device__ __forceinline__ void mma_tf32(float* d, const uint32_t* a,
                                         uint32_t b0, uint32_t b1) {
    asm volatile(
        "mma.sync.aligned.m16n8k8.row.col.f32.tf32.tf32.f32 "
        "{%0,%1,%2,%3}, {%4,%5,%6,%7}, {%8,%9}, {%0,%1,%2,%3};"
        : "+f"(d[0]), "+f"(d[1]), "+f"(d[2]), "+f"(d[3])
        : "r"(a[0]), "r"(a[1]), "r"(a[2]), "r"(a[3]), "r"(b0), "r"(b1));
}

__device__ __forceinline__ void ldsm4(uint32_t* r, uint32_t addr) {
    asm volatile("ldmatrix.sync.aligned.m8n8.x4.shared.b16 {%0,%1,%2,%3}, [%4];"
                 : "=r"(r[0]), "=r"(r[1]), "=r"(r[2]), "=r"(r[3])
                 : "r"(addr));
}

// ---------------- pre-conversion kernels ----------------
__global__ void pack_qkv(const float* __restrict__ Wq, const float* __restrict__ bq,
                         const float* __restrict__ Wk, const float* __restrict__ bk,
                         const float* __restrict__ Wv, const float* __restrict__ bv)
{
    int idx = blockIdx.x * blockDim.x + threadIdx.x;
    if (idx >= NQKV * DMOD) return;
    int n = idx >> 10, d = idx & 1023;       // n-major [n][k]
    int h = n / 192, j = n % 192, t = j >> 6, c = j & 63;
    const float* Wsrc = (t == 0) ? Wq : (t == 1) ? Wk : Wv;
    g_W[idx] = f2tf32(Wsrc[(h * DMOD + d) * DH + c]);
    if (idx < NQKV) {
        int nn = idx;
        int h2 = nn / 192, j2 = nn % 192, t2 = j2 >> 6, c2 = j2 & 63;
        const float* bsrc = (t2 == 0) ? bq : (t2 == 1) ? bk : bv;
        g_bias[nn] = bsrc[h2 * DH + c2];
    }
}

__global__ void pack_wo(const float* __restrict__ Wo)
{
    int idx = blockIdx.x * blockDim.x + threadIdx.x;
    if (idx >= DMOD * DMOD) return;
    int k = idx >> 10, n = idx & 1023;       // coalesced read
    g_Wo[n * DMOD + k] = f2tf32(Wo[idx]);    // n-major write
}

__global__ void cvt_q(const float* __restrict__ Q)
{
    int idx = blockIdx.x * blockDim.x + threadIdx.x;   // float4 granularity
    float4 v = *(const float4*)(Q + idx * 4);
    uint4 u = {f2tf32(v.x), f2tf32(v.y), f2tf32(v.z), f2tf32(v.w)};
    *(uint4*)(g_Atf + idx * 4) = u;
}

// ---------------- TF32 tensor-core GEMM: cp.async + ldmatrix ----------------
// Block tile 128x128x32; 8 warps (2x4), warp tile 64x32 via 4x4 m16n8k8.
// A smem [m][BK] stride 36; B smem [n][BK] stride 36 (both ldmatrix-fed).
#define BM 128
#define BN 128
#define BK 32
#define STAGES 3
#define LSTRIDE 36
#define A_WORDS (BM * LSTRIDE)              // 4608
#define B_WORDS (BN * LSTRIDE)              // 4608
#define STG_WORDS (A_WORDS + B_WORDS)       // 9216
#define GEMM_SMEM (STAGES * STG_WORDS * 4)  // 110592 B

template <int MODE>
__global__ void __launch_bounds__(256, 2) tf32_gemm(const float* __restrict__ biasparam,
                                                    float* __restrict__ C)
{
    constexpr int N = (MODE == 1) ? NQKV : DMOD;
    constexpr int K = DMOD;
    extern __shared__ uint32_t smem[];

    const uint32_t* Ag = (MODE == 1) ? g_Atf : (const uint32_t*)g_ctx;
    const uint32_t* Bg = (MODE == 1) ? g_W   : g_Wo;

    int tid = threadIdx.x;
    int warp = tid >> 5, lane = tid & 31;
    int wm = warp >> 2, wn = warp & 3;
    int g = lane >> 2, tg = lane & 3;
    int rowBase = blockIdx.y * BM;
    int colBase = blockIdx.x * BN;

    uint32_t sbase = smem_u32(smem);

    // ldmatrix per-lane byte offsets
    // A x4 tiles: (m0-7,klo)(m8-15,klo)(m0-7,khi)(m8-15,khi)
    uint32_t aoff = ((((lane >> 3) & 1) * 8 + (lane & 7)) * LSTRIDE + (lane >> 4) * 4) * 4;
    // B x4 tiles: (n0-7,klo)(n0-7,khi)(n8-15,klo)(n8-15,khi)
    uint32_t boff = (((lane >> 4) * 8 + (lane & 7)) * LSTRIDE + ((lane >> 3) & 1) * 4) * 4;

    float acc[4][4][4];
#pragma unroll
    for (int mi = 0; mi < 4; mi++)
#pragma unroll
        for (int ni = 0; ni < 4; ni++)
#pragma unroll
            for (int r = 0; r < 4; r++) acc[mi][ni][r] = 0.f;

    const int ntiles = K / BK;   // 32

    auto load_stage = [&](int kt) {
        int st = kt % STAGES;
        uint32_t sa = sbase + st * STG_WORDS * 4;
        uint32_t sb = sa + A_WORDS * 4;
        int k0 = kt * BK;
#pragma unroll
        for (int i = 0; i < 4; i++) {
            int c = tid + 256 * i;
            int row = c >> 3, seg = c & 7;
            cp16(sa + (row * LSTRIDE + seg * 4) * 4,
                 Ag + (size_t)(rowBase + row) * K + k0 + seg * 4);
        }
#pragma unroll
        for (int i = 0; i < 4; i++) {
            int c = tid + 256 * i;
            int row = c >> 3, seg = c & 7;
            cp16(sb + (row * LSTRIDE + seg * 4) * 4,
                 Bg + (size_t)(colBase + row) * K + k0 + seg * 4);
        }
        CP_COMMIT();
    };

#pragma unroll
    for (int kt = 0; kt < STAGES - 1; kt++) load_stage(kt);

    for (int kt = 0; kt < ntiles; kt++) {
        CP_WAIT(STAGES - 2);
        __syncthreads();
        if (kt + STAGES - 1 < ntiles) load_stage(kt + STAGES - 1);
        else CP_COMMIT();

        int st = kt % STAGES;
        uint32_t asu = sbase + st * STG_WORDS * 4;
        uint32_t bsu = asu + A_WORDS * 4;

#pragma unroll
        for (int ks = 0; ks < 4; ks++) {
            uint32_t afrag[4][4], bfrag[4][2];
#pragma unroll
            for (int mi = 0; mi < 4; mi++)
                ldsm4(afrag[mi],
                      asu + (((wm * 64 + mi * 16) * LSTRIDE + ks * 8) * 4) + aoff);
#pragma unroll
            for (int np = 0; np < 2; np++) {
                uint32_t tmp[4];
                ldsm4(tmp, bsu + (((wn * 32 + np * 16) * LSTRIDE + ks * 8) * 4) + boff);
                bfrag[2 * np + 0][0] = tmp[0];
                bfrag[2 * np + 0][1] = tmp[1];
                bfrag[2 * np + 1][0] = tmp[2];
                bfrag[2 * np + 1][1] = tmp[3];
            }
#pragma unroll
            for (int mi = 0; mi < 4; mi++)
#pragma unroll
                for (int ni = 0; ni < 4; ni++)
                    mma_tf32(acc[mi][ni], afrag[mi], bfrag[ni][0], bfrag[ni][1]);
        }
    }

    // epilogue
#pragma unroll
    for (int mi = 0; mi < 4; mi++) {
#pragma unroll
        for (int ni = 0; ni < 4; ni++) {
            int r0 = rowBase + wm * 64 + mi * 16 + g;
            int cn = colBase + wn * 32 + ni * 8 + tg * 2;
            if (MODE == 0) {
                float2 bv = *(const float2*)&biasparam[cn];
                float2 o0 = {acc[mi][ni][0] + bv.x, acc[mi][ni][1] + bv.y};
                float2 o1 = {acc[mi][ni][2] + bv.x, acc[mi][ni][3] + bv.y};
                *(float2*)&C[(size_t)r0 * N + cn] = o0;
                *(float2*)&C[(size_t)(r0 + 8) * N + cn] = o1;
            } else {
#pragma unroll
                for (int e = 0; e < 4; e++) {
                    int r = r0 + (e >> 1) * 8;
                    int n = cn + (e & 1);
                    int s = r >> 3, b = r & 7;
                    int h = n / 192, jj = n % 192, ty = jj >> 6, c = jj & 63;
                    float val = acc[mi][ni][e] + g_bias[n];
                    float* bufp = (ty == 0) ? g_q : (ty == 1) ? g_k : g_v;
                    bufp[((h * BB + b) * SS + s) * DH + c] =
                        __uint_as_float(f2tf32(val));   // store tf32 bits
                }
            }
        }
    }
}

// ---------------- TF32 mma.sync flash attention (unchanged) ----------------
#define KSTRIDE 68
#define VSTRIDE 72
#define PSTRIDE 68

__global__ void __launch_bounds__(256) flash_tf32()
{
    extern __shared__ uint32_t sm[];
    uint32_t* Ks = sm;
    uint32_t* Vs = Ks + 64 * KSTRIDE;
    uint32_t* Ps = Vs + 64 * VSTRIDE;

    int tid = threadIdx.x;
    int warp = tid >> 5, lane = tid & 31;
    int g = lane >> 2, tg = lane & 3;
    int qx = blockIdx.x;
    int hb = blockIdx.y;
    int h = hb >> 3, b = hb & 7;
    int qs0 = qx * 128;
    int wr = warp * 16;

    const float* qg  = g_q + ((size_t)(h * BB + b) * SS + qs0) * DH;
    const uint32_t* kg0 = (const uint32_t*)g_k + (size_t)(h * BB + b) * SS * DH;
    const uint32_t* vg0 = (const uint32_t*)g_v + (size_t)(h * BB + b) * SS * DH;

    uint32_t aq[8][4];
#pragma unroll
    for (int ki = 0; ki < 8; ki++) {
        const float* qp = qg + (wr + g) * DH + ki * 8 + tg;
        aq[ki][0] = __float_as_uint(qp[0] * 0.125f);
        aq[ki][1] = __float_as_uint(qp[8 * DH] * 0.125f);
        aq[ki][2] = __float_as_uint(qp[4] * 0.125f);
        aq[ki][3] = __float_as_uint(qp[8 * DH + 4] * 0.125f);
    }

    float o[8][4];
#pragma unroll
    for (int ni = 0; ni < 8; ni++)
#pragma unroll
        for (int e = 0; e < 4; e++) o[ni][e] = 0.f;
    float m_lo = -INFINITY, m_hi = -INFINITY, l_lo = 0.f, l_hi = 0.f;

    const int nkt = 2 * (qx + 1);
    for (int kt = 0; kt < nkt; kt++) {
        const uint32_t* kg = kg0 + (size_t)kt * 64 * DH;
        const uint32_t* vg = vg0 + (size_t)kt * 64 * DH;
        __syncthreads();
#pragma unroll
        for (int t = 0; t < 4; t++) {
            int f = tid + t * 256;
            int row = f >> 4, c4 = (f & 15) << 2;
            uint4 kv = *(const uint4*)(kg + row * DH + c4);
            uint32_t* kp = Ks + row * KSTRIDE + c4;
            kp[0] = kv.x; kp[1] = kv.y; kp[2] = kv.z; kp[3] = kv.w;
            uint4 vv = *(const uint4*)(vg + row * DH + c4);
            uint32_t* vp = Vs + row * VSTRIDE + c4;
            vp[0] = vv.x; vp[1] = vv.y; vp[2] = vv.z; vp[3] = vv.w;
        }
        __syncthreads();

        float sc[8][4];
#pragma unroll
        for (int ni = 0; ni < 8; ni++)
#pragma unroll
            for (int e = 0; e < 4; e++) sc[ni][e] = 0.f;
#pragma unroll
        for (int ki = 0; ki < 8; ki++) {
#pragma unroll
            for (int ni = 0; ni < 8; ni++) {
                const uint32_t* kb = Ks + (ni * 8 + g) * KSTRIDE + ki * 8 + tg;
                mma_tf32(sc[ni], aq[ki], kb[0], kb[4]);
            }
        }

        if (kt * 64 + 63 > qs0 + wr) {
            int rlo = qs0 + wr + g, rhi = rlo + 8;
#pragma unroll
            for (int ni = 0; ni < 8; ni++) {
                int col = kt * 64 + ni * 8 + 2 * tg;
                if (col     > rlo) sc[ni][0] = -1e30f;
                if (col + 1 > rlo) sc[ni][1] = -1e30f;
                if (col     > rhi) sc[ni][2] = -1e30f;
                if (col + 1 > rhi) sc[ni][3] = -1e30f;
            }
        }

        float mx_lo = -1e30f, mx_hi = -1e30f;
#pragma unroll
        for (int ni = 0; ni < 8; ni++) {
            mx_lo = fmaxf(mx_lo, fmaxf(sc[ni][0], sc[ni][1]));
            mx_hi = fmaxf(mx_hi, fmaxf(sc[ni][2], sc[ni][3]));
        }
        mx_lo = fmaxf(mx_lo, __shfl_xor_sync(0xffffffffu, mx_lo, 1));
        mx_lo = fmaxf(mx_lo, __shfl_xor_sync(0xffffffffu, mx_lo, 2));
        mx_hi = fmaxf(mx_hi, __shfl_xor_sync(0xffffffffu, mx_hi, 1));
        mx_hi = fmaxf(mx_hi, __shfl_xor_sync(0xffffffffu, mx_hi, 2));

        float mn_lo = fmaxf(m_lo, mx_lo), mn_hi = fmaxf(m_hi, mx_hi);
        float al_lo = __expf(m_lo - mn_lo), al_hi = __expf(m_hi - mn_hi);
        m_lo = mn_lo; m_hi = mn_hi;

        float rs_lo = 0.f, rs_hi = 0.f;
        uint32_t* plo = Ps + (wr + g) * PSTRIDE + 2 * tg;
        uint32_t* phi = Ps + (wr + g + 8) * PSTRIDE + 2 * tg;
#pragma unroll
        for (int ni = 0; ni < 8; ni++) {
            float p0 = __expf(sc[ni][0] - mn_lo);
            float p1 = __expf(sc[ni][1] - mn_lo);
            float p2 = __expf(sc[ni][2] - mn_hi);
            float p3 = __expf(sc[ni][3] - mn_hi);
            rs_lo += p0 + p1;
            rs_hi += p2 + p3;
            plo[ni * 8 + 0] = f2tf32(p0);
            plo[ni * 8 + 1] = f2tf32(p1);
            phi[ni * 8 + 0] = f2tf32(p2);
            phi[ni * 8 + 1] = f2tf32(p3);
        }
        rs_lo += __shfl_xor_sync(0xffffffffu, rs_lo, 1);
        rs_lo += __shfl_xor_sync(0xffffffffu, rs_lo, 2);
        rs_hi += __shfl_xor_sync(0xffffffffu, rs_hi, 1);
        rs_hi += __shfl_xor_sync(0xffffffffu, rs_hi, 2);
        l_lo = l_lo * al_lo + rs_lo;
        l_hi = l_hi * al_hi + rs_hi;

#pragma unroll
        for (int ni = 0; ni < 8; ni++) {
            o[ni][0] *= al_lo; o[ni][1] *= al_lo;
            o[ni][2] *= al_hi; o[ni][3] *= al_hi;
        }
        __syncwarp();

#pragma unroll
        for (int ki = 0; ki < 8; ki++) {
            uint32_t ap[4];
            ap[0] = Ps[(wr + g) * PSTRIDE + ki * 8 + tg];
            ap[1] = Ps[(wr + g + 8) * PSTRIDE + ki * 8 + tg];
            ap[2] = Ps[(wr + g) * PSTRIDE + ki * 8 + tg + 4];
            ap[3] = Ps[(wr + g + 8) * PSTRIDE + ki * 8 + tg + 4];
#pragma unroll
            for (int ni = 0; ni < 8; ni++) {
                uint32_t b0 = Vs[(ki * 8 + tg) * VSTRIDE + ni * 8 + g];
                uint32_t b1 = Vs[(ki * 8 + tg + 4) * VSTRIDE + ni * 8 + g];
                mma_tf32(o[ni], ap, b0, b1);
            }
        }
    }

    float inv_lo = 1.f / l_lo, inv_hi = 1.f / l_hi;
    int s = qs0 + wr + g;
    int cb = h * DH + 2 * tg;
    uint32_t* ctx = (uint32_t*)g_ctx;
#pragma unroll
    for (int ni = 0; ni < 8; ni++) {
        uint2 w0 = {f2tf32(o[ni][0] * inv_lo), f2tf32(o[ni][1] * inv_lo)};
        uint2 w1 = {f2tf32(o[ni][2] * inv_hi), f2tf32(o[ni][3] * inv_hi)};
        *(uint2*)&ctx[(size_t)(s * BB + b) * DMOD + cb + ni * 8] = w0;
        *(uint2*)&ctx[(size_t)((s + 8) * BB + b) * DMOD + cb + ni * 8] = w1;
    }
}

// ---------------- launch ----------------
extern "C" void kernel_launch(void* const* d_in, const int* in_sizes, int n_in,
                              void* d_out, int out_size)
{
    const float* Q  = (const float*)d_in[0];
    const float* Wq = (const float*)d_in[1];
    const float* bq = (const float*)d_in[2];
    const float* Wk = (const float*)d_in[3];
    const float* bk = (const float*)d_in[4];
    const float* Wv = (const float*)d_in[5];
    const float* bv = (const float*)d_in[6];
    const float* Wo = (const float*)d_in[7];
    const float* bo = (const float*)d_in[8];
    float* out = (float*)d_out;

    const int M = SS * BB;  // 8192

    // 1) pre-convert weights + input to tf32 bits (weights n-major)
    pack_qkv<<<(NQKV * DMOD + 255) / 256, 256>>>(Wq, bq, Wk, bk, Wv, bv);
    pack_wo<<<(DMOD * DMOD + 255) / 256, 256>>>(Wo);
    cvt_q<<<(M * DMOD / 4 + 255) / 256, 256>>>(Q);

    // 2) QKV projection: (8192x1024) @ (1024x3072) -> q/k/v (tf32 bits)
    {
        cudaFuncSetAttribute(tf32_gemm<1>, cudaFuncAttributeMaxDynamicSharedMemorySize,
                             GEMM_SMEM);
        dim3 grid(NQKV / BN, M / BM);
        tf32_gemm<1><<<grid, 256, GEMM_SMEM>>>(nullptr, nullptr);
    }

    // 3) causal flash attention -> g_ctx (tf32 bits)
    {
        size_t smem = (size_t)(64 * KSTRIDE + 64 * VSTRIDE + 128 * PSTRIDE) * 4;
        cudaFuncSetAttribute(flash_tf32, cudaFuncAttributeMaxDynamicSharedMemorySize,
                             (int)smem);
        flash_tf32<<<dim3(SS / 128, HH * BB), 256, smem>>>();
    }

    // 4) output projection: ctx (8192x1024) @ Wo + bo -> out (fp32)
    {
        cudaFuncSetAttribute(tf32_gemm<0>, cudaFuncAttributeMaxDynamicSharedMemorySize,
                             GEMM_SMEM);
        dim3 grid(DMOD / BN, M / BM);
        tf32_gemm<0><<<grid, 256, GEMM_SMEM>>>(bo, out);
    }
}